// round 7
// baseline (speedup 1.0000x reference)
#include <cuda_runtime.h>
#include <cuda_bf16.h>
#include <mma.h>
#include <math.h>

using namespace nvcuda;

#define QLENC   512
#define KLENC   1024
#define BSZC    8
#define NHEADC  16
#define DHEADC  64
#define DMODELC 1024
#define DINNERC 4096
#define NTOKC   32000
#define NLAYERC 6
#define NT      4096
#define KT      8192
#define NTILE_V (NTOKC / 128)   // 250 logits column tiles

typedef __nv_bfloat16 bf;

__device__ __forceinline__ float tf32r(float x) {
    float r;
    asm("cvt.rna.tf32.f32 %0, %1;" : "=f"(r) : "f"(x));
    return r;
}

// ------------------------- scratch (device globals) ------------------------
__device__ float g_core [NT * DMODELC];
__device__ float g_coreR[NT * DMODELC];
__device__ float g_q  [NT * DMODELC];
__device__ float g_qw [NT * DMODELC];
__device__ float g_qr [NT * DMODELC];
__device__ float g_kv [KT * 2 * DMODELC];
__device__ float g_rk [KLENC * DMODELC];
__device__ float g_pos[KLENC * DMODELC];
__device__ float g_bd [67108864];          // [n][4096][1024]
__device__ float g_vec[NT * DMODELC];
__device__ float g_tmp[NT * DMODELC];
__device__ float g_h1 [NT * DINNERC];
__device__ bf    g_embb [NTOKC * DMODELC];
__device__ bf    g_coreb[NT * DMODELC];
__device__ float g_pmax[NT * NTILE_V];
__device__ float g_psum[NT * NTILE_V];
__device__ float g_tgt [NT];

// ------------------------------ cp.async helpers ---------------------------
__device__ __forceinline__ void cp16(void* dst, const void* src) {
    unsigned d = (unsigned)__cvta_generic_to_shared(dst);
    asm volatile("cp.async.cg.shared.global [%0], [%1], 16;\n" :: "r"(d), "l"(src));
}
__device__ __forceinline__ void cp_commit() { asm volatile("cp.async.commit_group;\n"); }
__device__ __forceinline__ void cp_wait0()  { asm volatile("cp.async.wait_group 0;\n"); }

// ------------------------------- reductions --------------------------------
__device__ __forceinline__ float block_reduce_sum(float v) {
    __shared__ float sd[256];
    int tid = threadIdx.x;
    sd[tid] = v; __syncthreads();
    #pragma unroll
    for (int s = 128; s > 0; s >>= 1) {
        if (tid < s) sd[tid] += sd[tid + s];
        __syncthreads();
    }
    float r = sd[0]; __syncthreads();
    return r;
}

// --------------------- tf32 double-buffered wmma GEMM ----------------------
// CVTA/CVTB: convert that operand's fragments to tf32 in-loop (for operands
// not pre-rounded at the producer). RND: round output to tf32.
template<int BN, bool TB, int EPI, bool RND, bool CVTA, bool CVTB>
__global__ void __launch_bounds__(256) tgemm_k(
    const float* __restrict__ A, const float* __restrict__ B,
    float* __restrict__ C, const float* __restrict__ bias,
    int K, int lda, int ldb, int ldc,
    int batch2,
    long long sA1, long long sA2, long long sB1, long long sB2,
    long long sC1, long long sC2)
{
    constexpr int WARPS_N = BN / 32;
    constexpr int WARPS_M = 8 / WARPS_N;
    constexpr int MI = 128 / (WARPS_M * 16);
    constexpr int NI = 2;
    constexpr int A_LD  = 36;
    constexpr int A_ELE = 128 * A_LD;
    constexpr int B_LD  = TB ? 36 : (BN + 4);
    constexpr int B_ELE = TB ? (BN * 36) : (32 * (BN + 4));

    int z = blockIdx.z;
    int z1 = z / batch2, z2 = z - z1 * batch2;
    A += z1 * sA1 + z2 * sA2;
    B += z1 * sB1 + z2 * sB2;
    C += z1 * sC1 + z2 * sC2;

    extern __shared__ float smem[];
    float* sA[2] = { smem, smem + A_ELE };
    float* sB[2] = { smem + 2 * A_ELE, smem + 2 * A_ELE + B_ELE };
    float* stage = smem + 2 * A_ELE + 2 * B_ELE;

    const int tid  = threadIdx.x;
    const int m0   = blockIdx.y * 128, n0 = blockIdx.x * BN;
    const int warp = tid >> 5, lane = tid & 31;
    const int wm   = warp / WARPS_N, wn = warp % WARPS_N;
    const int wmB  = wm * MI * 16, wnB = wn * 32;

    wmma::fragment<wmma::accumulator, 16, 16, 8, float> acc[MI][NI];
    #pragma unroll
    for (int i = 0; i < MI; i++)
        #pragma unroll
        for (int j = 0; j < NI; j++)
            wmma::fill_fragment(acc[i][j], 0.f);

    auto loadA = [&](int buf, int k0) {
        #pragma unroll
        for (int p = 0; p < 4; p++) {
            int row = p * 32 + (tid >> 3), col = (tid & 7) * 4;
            cp16(&sA[buf][row * A_LD + col],
                 A + (long long)(m0 + row) * lda + k0 + col);
        }
    };
    auto loadB = [&](int buf, int k0) {
        if (TB) {
            #pragma unroll
            for (int p = 0; p < BN / 32; p++) {
                int row = p * 32 + (tid >> 3), col = (tid & 7) * 4;
                cp16(&sB[buf][row * B_LD + col],
                     B + (long long)(n0 + row) * ldb + k0 + col);
            }
        } else {
            constexpr int TPR = BN / 4;
            constexpr int RPP = 256 / TPR;
            #pragma unroll
            for (int p = 0; p < 32 / RPP; p++) {
                int row = p * RPP + tid / TPR;
                int col = (tid % TPR) * 4;
                cp16(&sB[buf][row * B_LD + col],
                     B + (long long)(k0 + row) * ldb + n0 + col);
            }
        }
    };
    auto compute = [&](int buf) {
        #pragma unroll
        for (int kk = 0; kk < 4; kk++) {
            wmma::fragment<wmma::matrix_a, 16, 16, 8, wmma::precision::tf32,
                           wmma::row_major> af[MI];
            #pragma unroll
            for (int i = 0; i < MI; i++) {
                wmma::load_matrix_sync(af[i],
                    &sA[buf][(wmB + i * 16) * A_LD + kk * 8], A_LD);
                if (CVTA) {
                    #pragma unroll
                    for (int e = 0; e < af[i].num_elements; e++)
                        af[i].x[e] = wmma::__float_to_tf32(af[i].x[e]);
                }
            }
            #pragma unroll
            for (int j = 0; j < NI; j++) {
                if (TB) {
                    wmma::fragment<wmma::matrix_b, 16, 16, 8, wmma::precision::tf32,
                                   wmma::col_major> bfg;
                    wmma::load_matrix_sync(bfg,
                        &sB[buf][(wnB + j * 16) * B_LD + kk * 8], B_LD);
                    if (CVTB) {
                        #pragma unroll
                        for (int e = 0; e < bfg.num_elements; e++)
                            bfg.x[e] = wmma::__float_to_tf32(bfg.x[e]);
                    }
                    #pragma unroll
                    for (int i = 0; i < MI; i++)
                        wmma::mma_sync(acc[i][j], af[i], bfg, acc[i][j]);
                } else {
                    wmma::fragment<wmma::matrix_b, 16, 16, 8, wmma::precision::tf32,
                                   wmma::row_major> bfg;
                    wmma::load_matrix_sync(bfg,
                        &sB[buf][(kk * 8) * B_LD + wnB + j * 16], B_LD);
                    if (CVTB) {
                        #pragma unroll
                        for (int e = 0; e < bfg.num_elements; e++)
                            bfg.x[e] = wmma::__float_to_tf32(bfg.x[e]);
                    }
                    #pragma unroll
                    for (int i = 0; i < MI; i++)
                        wmma::mma_sync(acc[i][j], af[i], bfg, acc[i][j]);
                }
            }
        }
    };

    int buf = 0;
    loadA(0, 0); loadB(0, 0); cp_commit();
    for (int k0 = 0; k0 < K; k0 += 32) {
        cp_wait0();
        __syncthreads();
        int nk = k0 + 32;
        if (nk < K) { loadA(buf ^ 1, nk); loadB(buf ^ 1, nk); }
        cp_commit();
        compute(buf);
        buf ^= 1;
    }

    if (EPI == 0 && !RND) {
        #pragma unroll
        for (int i = 0; i < MI; i++)
            #pragma unroll
            for (int j = 0; j < NI; j++) {
                int row0 = m0 + wmB + i * 16;
                int col0 = n0 + wnB + j * 16;
                wmma::store_matrix_sync(C + (long long)row0 * ldc + col0,
                                        acc[i][j], ldc, wmma::mem_row_major);
            }
    } else {
        float* st = stage + warp * 256;
        #pragma unroll
        for (int i = 0; i < MI; i++)
            #pragma unroll
            for (int j = 0; j < NI; j++) {
                int row0 = m0 + wmB + i * 16;
                int col0 = n0 + wnB + j * 16;
                wmma::store_matrix_sync(st, acc[i][j], 16, wmma::mem_row_major);
                __syncwarp();
                #pragma unroll
                for (int e = 0; e < 8; e++) {
                    int idx = lane * 8 + e;
                    int r = idx >> 4, c = idx & 15;
                    float v = st[idx];
                    int col = col0 + c;
                    if (EPI >= 1) v += bias[col];
                    if (EPI == 2) v = fmaxf(v, 0.f);
                    if (RND)      v = tf32r(v);
                    C[(long long)(row0 + r) * ldc + col] = v;
                }
                __syncwarp();
            }
    }
}

// --------------------------- fused attention -------------------------------
// Per CTA: (i-tile of 128 q rows, batch b, head n). Online softmax over
// j-tiles of 128 keys. S = qw@k^T (wmma tf32); score = (S + shifted BD)/8,
// causal mask; P = exp(score - m); O += P@V (wmma); epilogue O/l -> vec.
__global__ void __launch_bounds__(256) fattn_k(
    const float* __restrict__ qw, const float* __restrict__ kv,
    const float* __restrict__ bd, float* __restrict__ vec)
{
    extern __shared__ float sm[];
    float* sQ = sm;                       // 128 x 68
    float* sK = sQ + 128 * 68;            // 128 x 68
    float* sV = sK + 128 * 68;            // 128 x 68
    float* sS = sV + 128 * 68;            // 128 x 132
    float* sO = sS + 128 * 132;           // 128 x 68
    float* sStage = sO + 128 * 68;        // 8 x 256
    float* sMrow = sStage + 8 * 256;      // 128
    float* sLrow = sMrow + 128;           // 128
    float* sPm   = sLrow + 128;           // 128 x 2
    float* sPs   = sPm + 256;             // 128 x 2

    const int tid  = threadIdx.x;
    const int warp = tid >> 5, lane = tid & 31;
    const int i0 = blockIdx.x * 128;
    const int bn = blockIdx.y;
    const int b = bn >> 4, n = bn & 15;
    const int r = tid >> 1, h = tid & 1;
    const int i = i0 + r;

    // load Q tile, zero O, init row stats
    {
        const float* src = qw + ((long long)(i * 8 + b)) * DMODELC + n * 64 + h * 32;
        float* dq = sQ + r * 68 + h * 32;
        float* doo = sO + r * 68 + h * 32;
        #pragma unroll
        for (int c = 0; c < 32; c += 4) {
            *(float4*)(dq + c) = *(const float4*)(src + c);
            float4 zz = make_float4(0.f, 0.f, 0.f, 0.f);
            *(float4*)(doo + c) = zz;
        }
        if (tid < 128) { sMrow[tid] = -1e30f; sLrow[tid] = 0.f; }
    }
    __syncthreads();

    const int n_jt = (i0 + 639) / 128 + 1;
    const float* bdrow = bd + ((long long)n * NT + (i * 8 + b)) * KLENC;

    for (int jt = 0; jt < n_jt; jt++) {
        const int j0 = jt * 128;
        // load K/V tiles
        {
            const float* srcK = kv + ((long long)((j0 + r) * 8 + b)) * 2048 + n * 64 + h * 32;
            const float* srcV = srcK + DMODELC;
            float* dK = sK + r * 68 + h * 32;
            float* dV = sV + r * 68 + h * 32;
            #pragma unroll
            for (int c = 0; c < 32; c += 4) {
                *(float4*)(dK + c) = *(const float4*)(srcK + c);
                *(float4*)(dV + c) = *(const float4*)(srcV + c);
            }
        }
        __syncthreads();

        // S = Q @ K^T  (warp: rows (warp>>1)*32, cols (warp&1)*64)
        {
            const int wms = (warp >> 1) * 32, wns = (warp & 1) * 64;
            wmma::fragment<wmma::accumulator, 16, 16, 8, float> acc[2][4];
            #pragma unroll
            for (int a = 0; a < 2; a++)
                #pragma unroll
                for (int bb2 = 0; bb2 < 4; bb2++)
                    wmma::fill_fragment(acc[a][bb2], 0.f);
            #pragma unroll
            for (int kk = 0; kk < 8; kk++) {
                wmma::fragment<wmma::matrix_a, 16, 16, 8, wmma::precision::tf32,
                               wmma::row_major> af[2];
                #pragma unroll
                for (int a = 0; a < 2; a++)
                    wmma::load_matrix_sync(af[a], &sQ[(wms + a * 16) * 68 + kk * 8], 68);
                #pragma unroll
                for (int bb2 = 0; bb2 < 4; bb2++) {
                    wmma::fragment<wmma::matrix_b, 16, 16, 8, wmma::precision::tf32,
                                   wmma::col_major> bfg;
                    wmma::load_matrix_sync(bfg, &sK[(wns + bb2 * 16) * 68 + kk * 8], 68);
                    #pragma unroll
                    for (int a = 0; a < 2; a++)
                        wmma::mma_sync(acc[a][bb2], af[a], bfg, acc[a][bb2]);
                }
            }
            #pragma unroll
            for (int a = 0; a < 2; a++)
                #pragma unroll
                for (int bb2 = 0; bb2 < 4; bb2++)
                    wmma::store_matrix_sync(&sS[(wms + a * 16) * 132 + wns + bb2 * 16],
                                            acc[a][bb2], 132, wmma::mem_row_major);
        }
        __syncthreads();

        // sweep1: add shifted BD, scale, mask; partial max
        float* srow = sS + r * 132 + h * 64;
        const int jbase = j0 + h * 64;
        const int vlim = i + 512 - jbase;     // c <= vlim valid
        const int jjoff = jbase + 511 - i;
        float mx = -1e30f;
        for (int c = 0; c < 64; c++) {
            float v = -1e30f;
            if (c <= vlim) v = (srow[c] + bdrow[jjoff + c]) * 0.125f;
            srow[c] = v;
            mx = fmaxf(mx, v);
        }
        sPm[r * 2 + h] = mx;
        __syncthreads();
        float m_old = sMrow[r];
        float m_new = fmaxf(m_old, fmaxf(sPm[r * 2], sPm[r * 2 + 1]));
        float esc = expf(m_old - m_new);
        __syncwarp();
        if (h == 0) sMrow[r] = m_new;

        // sweep2: exp -> P (tf32-rounded); partial sum; scale O
        float ls = 0.f;
        for (int c = 0; c < 64; c++) {
            float v = srow[c];
            float e = (v > -5e29f) ? tf32r(expf(v - m_new)) : 0.f;
            srow[c] = e;
            ls += e;
        }
        sPs[r * 2 + h] = ls;
        {
            float* orow = sO + r * 68 + h * 32;
            #pragma unroll
            for (int c = 0; c < 32; c++) orow[c] *= esc;
        }
        __syncthreads();
        if (h == 0) sLrow[r] = sLrow[r] * esc + sPs[r * 2] + sPs[r * 2 + 1];

        // PV: O += P[128,128] @ V[128,64]  (warp: rows (warp>>1)*32, cols (warp&1)*32)
        {
            const int wmp = (warp >> 1) * 32, wnp = (warp & 1) * 32;
            wmma::fragment<wmma::accumulator, 16, 16, 8, float> acc[2][2];
            #pragma unroll
            for (int a = 0; a < 2; a++)
                #pragma unroll
                for (int bb2 = 0; bb2 < 2; bb2++)
                    wmma::fill_fragment(acc[a][bb2], 0.f);
            #pragma unroll
            for (int kk = 0; kk < 16; kk++) {
                wmma::fragment<wmma::matrix_a, 16, 16, 8, wmma::precision::tf32,
                               wmma::row_major> af[2];
                #pragma unroll
                for (int a = 0; a < 2; a++)
                    wmma::load_matrix_sync(af[a], &sS[(wmp + a * 16) * 132 + kk * 8], 132);
                #pragma unroll
                for (int bb2 = 0; bb2 < 2; bb2++) {
                    wmma::fragment<wmma::matrix_b, 16, 16, 8, wmma::precision::tf32,
                                   wmma::row_major> bfg;
                    wmma::load_matrix_sync(bfg, &sV[(kk * 8) * 68 + wnp + bb2 * 16], 68);
                    #pragma unroll
                    for (int a = 0; a < 2; a++)
                        wmma::mma_sync(acc[a][bb2], af[a], bfg, acc[a][bb2]);
                }
            }
            float* st = sStage + warp * 256;
            #pragma unroll
            for (int a = 0; a < 2; a++)
                #pragma unroll
                for (int bb2 = 0; bb2 < 2; bb2++) {
                    wmma::store_matrix_sync(st, acc[a][bb2], 16, wmma::mem_row_major);
                    __syncwarp();
                    #pragma unroll
                    for (int e = 0; e < 8; e++) {
                        int idx = lane * 8 + e;
                        int rr = idx >> 4, cc = idx & 15;
                        sO[(wmp + a * 16 + rr) * 68 + wnp + bb2 * 16 + cc] += st[idx];
                    }
                    __syncwarp();
                }
        }
        __syncthreads();
    }

    // epilogue: vec = tf32r(O / l)
    {
        float inv = 1.f / sLrow[r];
        float* orow = sO + r * 68 + h * 32;
        float* dst = vec + ((long long)(i * 8 + b)) * DMODELC + n * 64 + h * 32;
        #pragma unroll
        for (int c = 0; c < 32; c++) dst[c] = tf32r(orow[c] * inv);
    }
}

// ---------- bf16 logits GEMM with fused per-tile log-softmax partials ------
__global__ void __launch_bounds__(256) bgemm_loss_k(
    const bf* __restrict__ A, const bf* __restrict__ B,
    const int* __restrict__ target,
    float* __restrict__ pmax_out, float* __restrict__ psum_out,
    float* __restrict__ tgtlog,
    int K, int lda, int ldb)
{
    __shared__ bf sA[2][128 * 40];
    __shared__ bf sB[2][128 * 40];
    __shared__ float sPmB[128][4];
    __shared__ float sPsB[128][4];
    __shared__ float sMB[128];
    __shared__ float sStageB[8][256];

    const int tid  = threadIdx.x;
    const int m0   = blockIdx.y * 128, n0 = blockIdx.x * 128;
    const int warp = tid >> 5, lane = tid & 31;
    const int wm   = warp >> 2, wn = warp & 3;
    const int wmB  = wm * 64, wnB = wn * 32;

    wmma::fragment<wmma::accumulator, 16, 16, 16, float> acc[4][2];
    #pragma unroll
    for (int i = 0; i < 4; i++)
        #pragma unroll
        for (int j = 0; j < 2; j++)
            wmma::fill_fragment(acc[i][j], 0.f);

    auto loadAB = [&](int buf, int k0) {
        #pragma unroll
        for (int p = 0; p < 2; p++) {
            int row = p * 64 + (tid >> 2), col = (tid & 3) * 8;
            cp16(&sA[buf][row * 40 + col],
                 A + (long long)(m0 + row) * lda + k0 + col);
            cp16(&sB[buf][row * 40 + col],
                 B + (long long)(n0 + row) * ldb + k0 + col);
        }
    };
    auto compute = [&](int buf) {
        #pragma unroll
        for (int kk = 0; kk < 2; kk++) {
            wmma::fragment<wmma::matrix_a, 16, 16, 16, bf, wmma::row_major> af[4];
            #pragma unroll
            for (int i = 0; i < 4; i++)
                wmma::load_matrix_sync(af[i], &sA[buf][(wmB + i * 16) * 40 + kk * 16], 40);
            #pragma unroll
            for (int j = 0; j < 2; j++) {
                wmma::fragment<wmma::matrix_b, 16, 16, 16, bf, wmma::col_major> bfg;
                wmma::load_matrix_sync(bfg, &sB[buf][(wnB + j * 16) * 40 + kk * 16], 40);
                #pragma unroll
                for (int i = 0; i < 4; i++)
                    wmma::mma_sync(acc[i][j], af[i], bfg, acc[i][j]);
            }
        }
    };

    int buf = 0;
    loadAB(0, 0); cp_commit();
    for (int k0 = 0; k0 < K; k0 += 32) {
        cp_wait0();
        __syncthreads();
        int nk = k0 + 32;
        if (nk < K) loadAB(buf ^ 1, nk);
        cp_commit();
        compute(buf);
        buf ^= 1;
    }

    // ---- fused per-tile row max / sum-exp / target capture ----
    float* st = sStageB[warp];
    #pragma unroll
    for (int i = 0; i < 4; i++) {
        float mx = -1e30f;
        #pragma unroll
        for (int j = 0; j < 2; j++) {
            wmma::store_matrix_sync(st, acc[i][j], 16, wmma::mem_row_major);
            __syncwarp();
            if (lane < 16) {
                #pragma unroll
                for (int c = 0; c < 16; c++) mx = fmaxf(mx, st[lane * 16 + c]);
            }
            __syncwarp();
        }
        if (lane < 16) sPmB[wmB + i * 16 + lane][wn] = mx;
    }
    __syncthreads();
    if (tid < 128)
        sMB[tid] = fmaxf(fmaxf(sPmB[tid][0], sPmB[tid][1]),
                         fmaxf(sPmB[tid][2], sPmB[tid][3]));
    __syncthreads();
    #pragma unroll
    for (int i = 0; i < 4; i++) {
        int rloc = wmB + i * 16 + (lane & 15);
        float m = sMB[rloc];
        int t = m0 + rloc;
        int tg = (lane < 16) ? target[t] : -1;
        float sme = 0.f;
        #pragma unroll
        for (int j = 0; j < 2; j++) {
            wmma::store_matrix_sync(st, acc[i][j], 16, wmma::mem_row_major);
            __syncwarp();
            if (lane < 16) {
                #pragma unroll
                for (int c = 0; c < 16; c++) {
                    float x = st[lane * 16 + c];
                    sme += expf(x - m);
                    int col = n0 + wnB + j * 16 + c;
                    if (col == tg) tgtlog[t] = x;
                }
            }
            __syncwarp();
        }
        if (lane < 16) sPsB[rloc][wn] = sme;
    }
    __syncthreads();
    if (tid < 128) {
        float s = sPsB[tid][0] + sPsB[tid][1] + sPsB[tid][2] + sPsB[tid][3];
        long long idx = (long long)(m0 + tid) * NTILE_V + blockIdx.x;
        pmax_out[idx] = sMB[tid];
        psum_out[idx] = s;
    }
}

__global__ void loss_red_k(const float* __restrict__ pmax, const float* __restrict__ psum,
                           const float* __restrict__ tgt, float* __restrict__ out)
{
    int t = blockIdx.x;
    const float* pm = pmax + (long long)t * NTILE_V;
    const float* ps = psum + (long long)t * NTILE_V;
    __shared__ float sd[128];
    int tid = threadIdx.x;
    float m = -1e30f;
    for (int j = tid; j < NTILE_V; j += 128) m = fmaxf(m, pm[j]);
    sd[tid] = m; __syncthreads();
    #pragma unroll
    for (int s = 64; s > 0; s >>= 1) {
        if (tid < s) sd[tid] = fmaxf(sd[tid], sd[tid + s]);
        __syncthreads();
    }
    m = sd[0]; __syncthreads();
    float su = 0.f;
    for (int j = tid; j < NTILE_V; j += 128) su += ps[j] * expf(pm[j] - m);
    sd[tid] = su; __syncthreads();
    #pragma unroll
    for (int s = 64; s > 0; s >>= 1) {
        if (tid < s) sd[tid] += sd[tid + s];
        __syncthreads();
    }
    if (tid == 0) out[t] = -(tgt[t] - m - logf(sd[0]));
}

// ------------------------------ small kernels ------------------------------
__global__ void conv_k(const float* __restrict__ src, bf* __restrict__ dst, int n)
{
    int i = (blockIdx.x * 256 + threadIdx.x) * 4;
    if (i < n) {
        float4 v = *(const float4*)(src + i);
        dst[i + 0] = __float2bfloat16_rn(v.x);
        dst[i + 1] = __float2bfloat16_rn(v.y);
        dst[i + 2] = __float2bfloat16_rn(v.z);
        dst[i + 3] = __float2bfloat16_rn(v.w);
    }
}

__global__ void embed_k(const int* __restrict__ data, const float* __restrict__ emb,
                        float* __restrict__ core, float* __restrict__ coreR,
                        float* __restrict__ memout)
{
    int t = blockIdx.x;
    int tok = data[t];
    const float* src = emb + (long long)tok * DMODELC;
    #pragma unroll
    for (int r = 0; r < 4; r++) {
        int d = threadIdx.x + 256 * r;
        float v = src[d];
        core  [(long long)t * DMODELC + d] = v;
        coreR [(long long)t * DMODELC + d] = tf32r(v);
        memout[(long long)t * DMODELC + d] = v;
    }
}

__global__ void pos_k(float* __restrict__ pos)
{
    int k = blockIdx.x;
    float p = (float)(KLENC - 1 - k);
    #pragma unroll
    for (int r = 0; r < 4; r++) {
        int c = threadIdx.x + 256 * r;
        int j = (c < 512) ? c : (c - 512);
        float invf = 1.0f / powf(10000.0f, (2.0f * (float)j) / 1024.0f);
        float ang = p * invf;
        float v = (c < 512) ? sinf(ang) : cosf(ang);
        pos[(long long)k * DMODELC + c] = tf32r(v);
    }
}

__global__ void qwqr_k(const float* __restrict__ q, const float* __restrict__ rwb,
                       const float* __restrict__ rrb,
                       float* __restrict__ qw, float* __restrict__ qr)
{
    long long idx = (long long)blockIdx.x * 256 + threadIdx.x;
    int c = (int)(idx & 1023);
    float v = q[idx];
    qw[idx] = tf32r(v + rwb[c]);
    qr[idx] = tf32r(v + rrb[c]);
}

__global__ void ln_k(const float* __restrict__ x, const float* __restrict__ res,
                     const float* __restrict__ g, const float* __restrict__ bb,
                     float* __restrict__ dst, float* __restrict__ dstR,
                     float* __restrict__ dst2)
{
    long long t = blockIdx.x;
    const float* xr = x   + t * DMODELC;
    const float* rr = res + t * DMODELC;
    float v[4];
    float s = 0.f, sq = 0.f;
    #pragma unroll
    for (int r = 0; r < 4; r++) {
        int d = threadIdx.x + 256 * r;
        float u = xr[d] + rr[d];
        v[r] = u; s += u; sq += u * u;
    }
    float sum  = block_reduce_sum(s);
    float sums = block_reduce_sum(sq);
    float mean = sum * (1.0f / 1024.0f);
    float var  = sums * (1.0f / 1024.0f) - mean * mean;
    float rstd = rsqrtf(var + 1e-5f);
    #pragma unroll
    for (int r = 0; r < 4; r++) {
        int d = threadIdx.x + 256 * r;
        float y = (v[r] - mean) * rstd * g[d] + bb[d];
        dst [t * DMODELC + d] = y;
        dstR[t * DMODELC + d] = tf32r(y);
        if (dst2) dst2[t * DMODELC + d] = y;
    }
}

// ------------------------------ host dispatch ------------------------------
template<int BN, bool TB, int EPI, bool RND, bool CVTA, bool CVTB>
static inline void launch_tg(const float* A, const float* B, float* C,
    const float* bias, int gx, int gy, int gz,
    int K, int lda, int ldb, int ldc,
    int batch2 = 1,
    long long sA1 = 0, long long sA2 = 0,
    long long sB1 = 0, long long sB2 = 0,
    long long sC1 = 0, long long sC2 = 0)
{
    const int A_ELE = 128 * 36;
    const int B_ELE = TB ? (BN * 36) : (32 * (BN + 4));
    int smem = (2 * A_ELE + 2 * B_ELE + 2048) * 4;
    cudaFuncSetAttribute(tgemm_k<BN, TB, EPI, RND, CVTA, CVTB>,
                         cudaFuncAttributeMaxDynamicSharedMemorySize, smem);
    tgemm_k<BN, TB, EPI, RND, CVTA, CVTB><<<dim3(gx, gy, gz), 256, smem>>>(
        A, B, C, bias, K, lda, ldb, ldc, batch2, sA1, sA2, sB1, sB2, sC1, sC2);
}

extern "C" void kernel_launch(void* const* d_in, const int* in_sizes, int n_in,
                              void* d_out, int out_size)
{
    const int*   data   = (const int*)  d_in[0];
    const int*   target = (const int*)  d_in[1];
    const float* memory = (const float*)d_in[2];
    const float* emb_W  = (const float*)d_in[3];
    const float* rwb    = (const float*)d_in[4];
    const float* rrb    = (const float*)d_in[5];
    const float* Wq     = (const float*)d_in[6];
    const float* Wkv    = (const float*)d_in[7];
    const float* Wr     = (const float*)d_in[8];
    const float* Wo     = (const float*)d_in[9];
    const float* W1     = (const float*)d_in[10];
    const float* b1     = (const float*)d_in[11];
    const float* W2     = (const float*)d_in[12];
    const float* b2     = (const float*)d_in[13];
    const float* ln1g   = (const float*)d_in[14];
    const float* ln1b   = (const float*)d_in[15];
    const float* ln2g   = (const float*)d_in[16];
    const float* ln2b   = (const float*)d_in[17];
    float* out = (float*)d_out;

    float *core, *coreR, *q, *qw, *qr, *kv, *rk, *pos, *bdp, *vec, *tmp, *h1;
    float *pmax, *psum, *tgtl;
    bf *embb, *coreb;
    cudaGetSymbolAddress((void**)&core,  g_core);
    cudaGetSymbolAddress((void**)&coreR, g_coreR);
    cudaGetSymbolAddress((void**)&q,     g_q);
    cudaGetSymbolAddress((void**)&qw,    g_qw);
    cudaGetSymbolAddress((void**)&qr,    g_qr);
    cudaGetSymbolAddress((void**)&kv,    g_kv);
    cudaGetSymbolAddress((void**)&rk,    g_rk);
    cudaGetSymbolAddress((void**)&pos,   g_pos);
    cudaGetSymbolAddress((void**)&bdp,   g_bd);
    cudaGetSymbolAddress((void**)&vec,   g_vec);
    cudaGetSymbolAddress((void**)&tmp,   g_tmp);
    cudaGetSymbolAddress((void**)&h1,    g_h1);
    cudaGetSymbolAddress((void**)&pmax,  g_pmax);
    cudaGetSymbolAddress((void**)&psum,  g_psum);
    cudaGetSymbolAddress((void**)&tgtl,  g_tgt);
    cudaGetSymbolAddress((void**)&embb,  g_embb);
    cudaGetSymbolAddress((void**)&coreb, g_coreb);

    const long long LSLOT = (long long)NT * DMODELC;
    float* mems_out = out + NT;

    embed_k<<<NT, 256>>>(data, emb_W, core, coreR, mems_out);
    pos_k<<<KLENC, 256>>>(pos);
    conv_k<<<(NTOKC * DMODELC) / 1024, 256>>>(emb_W, embb, NTOKC * DMODELC);

    const int FATTN_SMEM = (128 * 68 * 4 + 128 * 132 + 8 * 256 + 128 * 2 + 256 * 2) * 4;
    cudaFuncSetAttribute(fattn_k, cudaFuncAttributeMaxDynamicSharedMemorySize, FATTN_SMEM);

    for (int l = 0; l < NLAYERC; l++) {
        const float* Wq_l  = Wq  + (long long)l * DMODELC * DMODELC;
        const float* Wkv_l = Wkv + (long long)l * DMODELC * 2 * DMODELC;
        const float* Wr_l  = Wr  + (long long)l * DMODELC * DMODELC;
        const float* Wo_l  = Wo  + (long long)l * DMODELC * DMODELC;
        const float* W1_l  = W1  + (long long)l * DMODELC * DINNERC;
        const float* b1_l  = b1  + (long long)l * DINNERC;
        const float* W2_l  = W2  + (long long)l * DINNERC * DMODELC;
        const float* b2_l  = b2  + (long long)l * DMODELC;
        const float* mem_l = memory + (long long)l * LSLOT;

        // kv rows 0..4095 (memory tokens): A unrounded -> CVTA
        launch_tg<128, false, 0, true, true, true>(mem_l, Wkv_l, kv, nullptr,
            2 * DMODELC / 128, 32, 1, DMODELC, DMODELC, 2 * DMODELC, 2 * DMODELC);
        // kv rows 4096..8191 (current tokens)
        launch_tg<128, false, 0, true, false, true>(coreR, Wkv_l,
            kv + (long long)NT * 2 * DMODELC, nullptr,
            2 * DMODELC / 128, 32, 1, DMODELC, DMODELC, 2 * DMODELC, 2 * DMODELC);

        // q = coreR @ Wq
        launch_tg<128, false, 0, false, false, true>(coreR, Wq_l, q, nullptr,
            DMODELC / 128, NT / 128, 1, DMODELC, DMODELC, DMODELC, DMODELC);
        qwqr_k<<<(NT * DMODELC) / 256, 256>>>(q, rwb, rrb, qw, qr);

        // r_k = pos @ Wr (rounded out)
        launch_tg<128, false, 0, true, false, true>(pos, Wr_l, rk, nullptr,
            DMODELC / 128, KLENC / 128, 1, DMODELC, DMODELC, DMODELC, DMODELC);

        // BD_raw[n] = qr @ rk^T
        launch_tg<128, true, 0, false, false, false>(qr, rk, bdp, nullptr,
            KLENC / 128, NT / 128, NHEADC,
            DHEADC, DMODELC, DMODELC, KLENC,
            NHEADC,
            0, DHEADC, 0, DHEADC, 0, (long long)NT * KLENC);

        // fused attention: AC + shift-BD + softmax + PV
        fattn_k<<<dim3(QLENC / 128, BSZC * NHEADC), 256, FATTN_SMEM>>>(qw, kv, bdp, vec);

        // attn_out = vec @ Wo
        launch_tg<128, false, 0, false, false, true>(vec, Wo_l, tmp, nullptr,
            DMODELC / 128, NT / 128, 1, DMODELC, DMODELC, DMODELC, DMODELC);

        ln_k<<<NT, 256>>>(core, tmp, ln1g + l * DMODELC, ln1b + l * DMODELC,
                          core, coreR, nullptr);

        // h1 = relu(coreR @ W1 + b1) (rounded out)
        launch_tg<128, false, 2, true, false, true>(coreR, W1_l, h1, b1_l,
            DINNERC / 128, NT / 128, 1, DMODELC, DMODELC, DINNERC, DINNERC);

        // ff = h1 @ W2 + b2
        launch_tg<128, false, 1, false, false, true>(h1, W2_l, tmp, b2_l,
            DMODELC / 128, NT / 128, 1, DINNERC, DINNERC, DMODELC, DMODELC);

        float* memout = (l < NLAYERC - 1) ? (mems_out + (long long)(l + 1) * LSLOT)
                                          : nullptr;
        ln_k<<<NT, 256>>>(core, tmp, ln2g + l * DMODELC, ln2b + l * DMODELC,
                          core, coreR, memout);
    }

    // logits GEMM fused with per-tile log-softmax partials, then reduce
    conv_k<<<(NT * DMODELC) / 1024, 256>>>(core, coreb, NT * DMODELC);
    bgemm_loss_k<<<dim3(NTILE_V, NT / 128, 1), 256>>>(
        coreb, embb, target, pmax, psum, tgtl, DMODELC, DMODELC, DMODELC);
    loss_red_k<<<NT, 128>>>(pmax, psum, tgtl, out);
}

// round 8
// speedup vs baseline: 1.1401x; 1.1401x over previous
#include <cuda_runtime.h>
#include <cuda_bf16.h>
#include <mma.h>
#include <math.h>

using namespace nvcuda;

#define QLENC   512
#define KLENC   1024
#define BSZC    8
#define NHEADC  16
#define DHEADC  64
#define DMODELC 1024
#define DINNERC 4096
#define NTOKC   32000
#define NLAYERC 6
#define NT      4096
#define KT      8192
#define NTILE_V (NTOKC / 128)   // 250 logits column tiles

typedef __nv_bfloat16 bf;

__device__ __forceinline__ float tf32r(float x) {
    float r;
    asm("cvt.rna.tf32.f32 %0, %1;" : "=f"(r) : "f"(x));
    return r;
}

// ------------------------- scratch (device globals) ------------------------
__device__ float g_core [NT * DMODELC];
__device__ float g_coreR[NT * DMODELC];
__device__ float g_q  [NT * DMODELC];
__device__ float g_qw [NT * DMODELC];
__device__ float g_qr [NT * DMODELC];
__device__ float g_kv [KT * 2 * DMODELC];
__device__ float g_rk [KLENC * DMODELC];
__device__ float g_pos[KLENC * DMODELC];
__device__ float g_scores[67108864];   // [b*16+n][512][1024]
__device__ float g_bd    [67108864];   // [n][4096][1024]
__device__ float g_probs [67108864];
__device__ float g_vec[NT * DMODELC];
__device__ float g_tmp[NT * DMODELC];
__device__ float g_h1 [NT * DINNERC];
__device__ bf    g_embb [NTOKC * DMODELC];
__device__ bf    g_coreb[NT * DMODELC];
__device__ float g_pmax[NT * NTILE_V];
__device__ float g_psum[NT * NTILE_V];
__device__ float g_tgt [NT];

// ------------------------------ cp.async helpers ---------------------------
__device__ __forceinline__ void cp16(void* dst, const void* src) {
    unsigned d = (unsigned)__cvta_generic_to_shared(dst);
    asm volatile("cp.async.cg.shared.global [%0], [%1], 16;\n" :: "r"(d), "l"(src));
}
__device__ __forceinline__ void cp_commit() { asm volatile("cp.async.commit_group;\n"); }
__device__ __forceinline__ void cp_wait0()  { asm volatile("cp.async.wait_group 0;\n"); }

// ------------------------------- reductions --------------------------------
__device__ __forceinline__ float block_reduce_max(float v) {
    __shared__ float sd[256];
    int tid = threadIdx.x;
    sd[tid] = v; __syncthreads();
    #pragma unroll
    for (int s = 128; s > 0; s >>= 1) {
        if (tid < s) sd[tid] = fmaxf(sd[tid], sd[tid + s]);
        __syncthreads();
    }
    float r = sd[0]; __syncthreads();
    return r;
}
__device__ __forceinline__ float block_reduce_sum(float v) {
    __shared__ float sd[256];
    int tid = threadIdx.x;
    sd[tid] = v; __syncthreads();
    #pragma unroll
    for (int s = 128; s > 0; s >>= 1) {
        if (tid < s) sd[tid] += sd[tid + s];
        __syncthreads();
    }
    float r = sd[0]; __syncthreads();
    return r;
}

// --------------------- tf32 double-buffered wmma GEMM ----------------------
template<int BN, bool TB, int EPI, bool RND, bool CVTA, bool CVTB>
__global__ void __launch_bounds__(256) tgemm_k(
    const float* __restrict__ A, const float* __restrict__ B,
    float* __restrict__ C, const float* __restrict__ bias,
    int K, int lda, int ldb, int ldc,
    int batch2,
    long long sA1, long long sA2, long long sB1, long long sB2,
    long long sC1, long long sC2)
{
    constexpr int WARPS_N = BN / 32;
    constexpr int WARPS_M = 8 / WARPS_N;
    constexpr int MI = 128 / (WARPS_M * 16);
    constexpr int NI = 2;
    constexpr int A_LD  = 36;
    constexpr int A_ELE = 128 * A_LD;
    constexpr int B_LD  = TB ? 36 : (BN + 4);
    constexpr int B_ELE = TB ? (BN * 36) : (32 * (BN + 4));

    int z = blockIdx.z;
    int z1 = z / batch2, z2 = z - z1 * batch2;
    A += z1 * sA1 + z2 * sA2;
    B += z1 * sB1 + z2 * sB2;
    C += z1 * sC1 + z2 * sC2;

    extern __shared__ float smem[];
    float* sA[2] = { smem, smem + A_ELE };
    float* sB[2] = { smem + 2 * A_ELE, smem + 2 * A_ELE + B_ELE };
    float* stage = smem + 2 * A_ELE + 2 * B_ELE;

    const int tid  = threadIdx.x;
    const int m0   = blockIdx.y * 128, n0 = blockIdx.x * BN;
    const int warp = tid >> 5, lane = tid & 31;
    const int wm   = warp / WARPS_N, wn = warp % WARPS_N;
    const int wmB  = wm * MI * 16, wnB = wn * 32;

    wmma::fragment<wmma::accumulator, 16, 16, 8, float> acc[MI][NI];
    #pragma unroll
    for (int i = 0; i < MI; i++)
        #pragma unroll
        for (int j = 0; j < NI; j++)
            wmma::fill_fragment(acc[i][j], 0.f);

    auto loadA = [&](int buf, int k0) {
        #pragma unroll
        for (int p = 0; p < 4; p++) {
            int row = p * 32 + (tid >> 3), col = (tid & 7) * 4;
            cp16(&sA[buf][row * A_LD + col],
                 A + (long long)(m0 + row) * lda + k0 + col);
        }
    };
    auto loadB = [&](int buf, int k0) {
        if (TB) {
            #pragma unroll
            for (int p = 0; p < BN / 32; p++) {
                int row = p * 32 + (tid >> 3), col = (tid & 7) * 4;
                cp16(&sB[buf][row * B_LD + col],
                     B + (long long)(n0 + row) * ldb + k0 + col);
            }
        } else {
            constexpr int TPR = BN / 4;
            constexpr int RPP = 256 / TPR;
            #pragma unroll
            for (int p = 0; p < 32 / RPP; p++) {
                int row = p * RPP + tid / TPR;
                int col = (tid % TPR) * 4;
                cp16(&sB[buf][row * B_LD + col],
                     B + (long long)(k0 + row) * ldb + n0 + col);
            }
        }
    };
    auto compute = [&](int buf) {
        #pragma unroll
        for (int kk = 0; kk < 4; kk++) {
            wmma::fragment<wmma::matrix_a, 16, 16, 8, wmma::precision::tf32,
                           wmma::row_major> af[MI];
            #pragma unroll
            for (int i = 0; i < MI; i++) {
                wmma::load_matrix_sync(af[i],
                    &sA[buf][(wmB + i * 16) * A_LD + kk * 8], A_LD);
                if (CVTA) {
                    #pragma unroll
                    for (int e = 0; e < af[i].num_elements; e++)
                        af[i].x[e] = wmma::__float_to_tf32(af[i].x[e]);
                }
            }
            #pragma unroll
            for (int j = 0; j < NI; j++) {
                if (TB) {
                    wmma::fragment<wmma::matrix_b, 16, 16, 8, wmma::precision::tf32,
                                   wmma::col_major> bfg;
                    wmma::load_matrix_sync(bfg,
                        &sB[buf][(wnB + j * 16) * B_LD + kk * 8], B_LD);
                    if (CVTB) {
                        #pragma unroll
                        for (int e = 0; e < bfg.num_elements; e++)
                            bfg.x[e] = wmma::__float_to_tf32(bfg.x[e]);
                    }
                    #pragma unroll
                    for (int i = 0; i < MI; i++)
                        wmma::mma_sync(acc[i][j], af[i], bfg, acc[i][j]);
                } else {
                    wmma::fragment<wmma::matrix_b, 16, 16, 8, wmma::precision::tf32,
                                   wmma::row_major> bfg;
                    wmma::load_matrix_sync(bfg,
                        &sB[buf][(kk * 8) * B_LD + wnB + j * 16], B_LD);
                    if (CVTB) {
                        #pragma unroll
                        for (int e = 0; e < bfg.num_elements; e++)
                            bfg.x[e] = wmma::__float_to_tf32(bfg.x[e]);
                    }
                    #pragma unroll
                    for (int i = 0; i < MI; i++)
                        wmma::mma_sync(acc[i][j], af[i], bfg, acc[i][j]);
                }
            }
        }
    };

    int buf = 0;
    loadA(0, 0); loadB(0, 0); cp_commit();
    for (int k0 = 0; k0 < K; k0 += 32) {
        cp_wait0();
        __syncthreads();
        int nk = k0 + 32;
        if (nk < K) { loadA(buf ^ 1, nk); loadB(buf ^ 1, nk); }
        cp_commit();
        compute(buf);
        buf ^= 1;
    }

    if (EPI == 0 && !RND) {
        #pragma unroll
        for (int i = 0; i < MI; i++)
            #pragma unroll
            for (int j = 0; j < NI; j++) {
                int row0 = m0 + wmB + i * 16;
                int col0 = n0 + wnB + j * 16;
                wmma::store_matrix_sync(C + (long long)row0 * ldc + col0,
                                        acc[i][j], ldc, wmma::mem_row_major);
            }
    } else {
        float* st = stage + warp * 256;
        #pragma unroll
        for (int i = 0; i < MI; i++)
            #pragma unroll
            for (int j = 0; j < NI; j++) {
                int row0 = m0 + wmB + i * 16;
                int col0 = n0 + wnB + j * 16;
                wmma::store_matrix_sync(st, acc[i][j], 16, wmma::mem_row_major);
                __syncwarp();
                #pragma unroll
                for (int e = 0; e < 8; e++) {
                    int idx = lane * 8 + e;
                    int r = idx >> 4, c = idx & 15;
                    float v = st[idx];
                    int col = col0 + c;
                    if (EPI >= 1) v += bias[col];
                    if (EPI == 2) v = fmaxf(v, 0.f);
                    if (RND)      v = tf32r(v);
                    C[(long long)(row0 + r) * ldc + col] = v;
                }
                __syncwarp();
            }
    }
}

// ---------- bf16 logits GEMM with fused per-tile log-softmax partials ------
__global__ void __launch_bounds__(256) bgemm_loss_k(
    const bf* __restrict__ A, const bf* __restrict__ B,
    const int* __restrict__ target,
    float* __restrict__ pmax_out, float* __restrict__ psum_out,
    float* __restrict__ tgtlog,
    int K, int lda, int ldb)
{
    __shared__ bf sA[2][128 * 40];
    __shared__ bf sB[2][128 * 40];
    __shared__ float sPmB[128][4];
    __shared__ float sPsB[128][4];
    __shared__ float sMB[128];
    __shared__ float sStageB[8][256];

    const int tid  = threadIdx.x;
    const int m0   = blockIdx.y * 128, n0 = blockIdx.x * 128;
    const int warp = tid >> 5, lane = tid & 31;
    const int wm   = warp >> 2, wn = warp & 3;
    const int wmB  = wm * 64, wnB = wn * 32;

    wmma::fragment<wmma::accumulator, 16, 16, 16, float> acc[4][2];
    #pragma unroll
    for (int i = 0; i < 4; i++)
        #pragma unroll
        for (int j = 0; j < 2; j++)
            wmma::fill_fragment(acc[i][j], 0.f);

    auto loadAB = [&](int buf, int k0) {
        #pragma unroll
        for (int p = 0; p < 2; p++) {
            int row = p * 64 + (tid >> 2), col = (tid & 3) * 8;
            cp16(&sA[buf][row * 40 + col],
                 A + (long long)(m0 + row) * lda + k0 + col);
            cp16(&sB[buf][row * 40 + col],
                 B + (long long)(n0 + row) * ldb + k0 + col);
        }
    };
    auto compute = [&](int buf) {
        #pragma unroll
        for (int kk = 0; kk < 2; kk++) {
            wmma::fragment<wmma::matrix_a, 16, 16, 16, bf, wmma::row_major> af[4];
            #pragma unroll
            for (int i = 0; i < 4; i++)
                wmma::load_matrix_sync(af[i], &sA[buf][(wmB + i * 16) * 40 + kk * 16], 40);
            #pragma unroll
            for (int j = 0; j < 2; j++) {
                wmma::fragment<wmma::matrix_b, 16, 16, 16, bf, wmma::col_major> bfg;
                wmma::load_matrix_sync(bfg, &sB[buf][(wnB + j * 16) * 40 + kk * 16], 40);
                #pragma unroll
                for (int i = 0; i < 4; i++)
                    wmma::mma_sync(acc[i][j], af[i], bfg, acc[i][j]);
            }
        }
    };

    int buf = 0;
    loadAB(0, 0); cp_commit();
    for (int k0 = 0; k0 < K; k0 += 32) {
        cp_wait0();
        __syncthreads();
        int nk = k0 + 32;
        if (nk < K) loadAB(buf ^ 1, nk);
        cp_commit();
        compute(buf);
        buf ^= 1;
    }

    float* st = sStageB[warp];
    #pragma unroll
    for (int i = 0; i < 4; i++) {
        float mx = -1e30f;
        #pragma unroll
        for (int j = 0; j < 2; j++) {
            wmma::store_matrix_sync(st, acc[i][j], 16, wmma::mem_row_major);
            __syncwarp();
            if (lane < 16) {
                #pragma unroll
                for (int c = 0; c < 16; c++) mx = fmaxf(mx, st[lane * 16 + c]);
            }
            __syncwarp();
        }
        if (lane < 16) sPmB[wmB + i * 16 + lane][wn] = mx;
    }
    __syncthreads();
    if (tid < 128)
        sMB[tid] = fmaxf(fmaxf(sPmB[tid][0], sPmB[tid][1]),
                         fmaxf(sPmB[tid][2], sPmB[tid][3]));
    __syncthreads();
    #pragma unroll
    for (int i = 0; i < 4; i++) {
        int rloc = wmB + i * 16 + (lane & 15);
        float m = sMB[rloc];
        int t = m0 + rloc;
        int tg = (lane < 16) ? target[t] : -1;
        float sme = 0.f;
        #pragma unroll
        for (int j = 0; j < 2; j++) {
            wmma::store_matrix_sync(st, acc[i][j], 16, wmma::mem_row_major);
            __syncwarp();
            if (lane < 16) {
                #pragma unroll
                for (int c = 0; c < 16; c++) {
                    float x = st[lane * 16 + c];
                    sme += expf(x - m);
                    int col = n0 + wnB + j * 16 + c;
                    if (col == tg) tgtlog[t] = x;
                }
            }
            __syncwarp();
        }
        if (lane < 16) sPsB[rloc][wn] = sme;
    }
    __syncthreads();
    if (tid < 128) {
        float s = sPsB[tid][0] + sPsB[tid][1] + sPsB[tid][2] + sPsB[tid][3];
        long long idx = (long long)(m0 + tid) * NTILE_V + blockIdx.x;
        pmax_out[idx] = sMB[tid];
        psum_out[idx] = s;
    }
}

__global__ void loss_red_k(const float* __restrict__ pmax, const float* __restrict__ psum,
                           const float* __restrict__ tgt, float* __restrict__ out)
{
    int t = blockIdx.x;
    const float* pm = pmax + (long long)t * NTILE_V;
    const float* ps = psum + (long long)t * NTILE_V;
    __shared__ float sd[128];
    int tid = threadIdx.x;
    float m = -1e30f;
    for (int j = tid; j < NTILE_V; j += 128) m = fmaxf(m, pm[j]);
    sd[tid] = m; __syncthreads();
    #pragma unroll
    for (int s = 64; s > 0; s >>= 1) {
        if (tid < s) sd[tid] = fmaxf(sd[tid], sd[tid + s]);
        __syncthreads();
    }
    m = sd[0]; __syncthreads();
    float su = 0.f;
    for (int j = tid; j < NTILE_V; j += 128) su += ps[j] * expf(pm[j] - m);
    sd[tid] = su; __syncthreads();
    #pragma unroll
    for (int s = 64; s > 0; s >>= 1) {
        if (tid < s) sd[tid] += sd[tid + s];
        __syncthreads();
    }
    if (tid == 0) out[t] = -(tgt[t] - m - logf(sd[0]));
}

// ------------------------------ small kernels ------------------------------
__global__ void conv_k(const float* __restrict__ src, bf* __restrict__ dst, int n)
{
    int i = (blockIdx.x * 256 + threadIdx.x) * 4;
    if (i < n) {
        float4 v = *(const float4*)(src + i);
        dst[i + 0] = __float2bfloat16_rn(v.x);
        dst[i + 1] = __float2bfloat16_rn(v.y);
        dst[i + 2] = __float2bfloat16_rn(v.z);
        dst[i + 3] = __float2bfloat16_rn(v.w);
    }
}

__global__ void embed_k(const int* __restrict__ data, const float* __restrict__ emb,
                        float* __restrict__ core, float* __restrict__ coreR,
                        float* __restrict__ memout)
{
    int t = blockIdx.x;
    int tok = data[t];
    const float* src = emb + (long long)tok * DMODELC;
    #pragma unroll
    for (int r = 0; r < 4; r++) {
        int d = threadIdx.x + 256 * r;
        float v = src[d];
        core  [(long long)t * DMODELC + d] = v;
        coreR [(long long)t * DMODELC + d] = tf32r(v);
        memout[(long long)t * DMODELC + d] = v;
    }
}

__global__ void pos_k(float* __restrict__ pos)
{
    int k = blockIdx.x;
    float p = (float)(KLENC - 1 - k);
    #pragma unroll
    for (int r = 0; r < 4; r++) {
        int c = threadIdx.x + 256 * r;
        int j = (c < 512) ? c : (c - 512);
        float invf = 1.0f / powf(10000.0f, (2.0f * (float)j) / 1024.0f);
        float ang = p * invf;
        float v = (c < 512) ? sinf(ang) : cosf(ang);
        pos[(long long)k * DMODELC + c] = tf32r(v);
    }
}

__global__ void qwqr_k(const float* __restrict__ q, const float* __restrict__ rwb,
                       const float* __restrict__ rrb,
                       float* __restrict__ qw, float* __restrict__ qr)
{
    long long idx = (long long)blockIdx.x * 256 + threadIdx.x;
    int c = (int)(idx & 1023);
    float v = q[idx];
    qw[idx] = tf32r(v + rwb[c]);
    qr[idx] = tf32r(v + rrb[c]);
}

__global__ void softmax_k(const float* __restrict__ scores, const float* __restrict__ bd,
                          float* __restrict__ probs)
{
    int i  = blockIdx.x;
    int bn = blockIdx.y;
    int b = bn >> 4, n = bn & 15;
    const float* ac = scores + (long long)bn * (QLENC * KLENC) + (long long)i * KLENC;
    float* pr = probs + (long long)bn * (QLENC * KLENC) + (long long)i * KLENC;
    const float* bdr = bd + (long long)n * ((long long)NT * KLENC)
                          + (long long)(i * BSZC + b) * KLENC;
    int shift = QLENC - 1 - i;
    int lim = i + 512;

    float vals[4];
    float lmax = -1e30f;
    #pragma unroll
    for (int r = 0; r < 4; r++) {
        int j = threadIdx.x + 256 * r;
        float v = -1e30f;
        if (j <= lim) v = (ac[j] + bdr[j + shift]) * 0.125f;
        vals[r] = v;
        lmax = fmaxf(lmax, v);
    }
    float rmax = block_reduce_max(lmax);
    float lsum = 0.f;
    #pragma unroll
    for (int r = 0; r < 4; r++) {
        float e = expf(vals[r] - rmax);
        vals[r] = e;
        lsum += e;
    }
    float rsum = block_reduce_sum(lsum);
    float inv = 1.0f / rsum;
    #pragma unroll
    for (int r = 0; r < 4; r++) {
        int j = threadIdx.x + 256 * r;
        pr[j] = tf32r(vals[r] * inv);
    }
}

__global__ void ln_k(const float* __restrict__ x, const float* __restrict__ res,
                     const float* __restrict__ g, const float* __restrict__ bb,
                     float* __restrict__ dst, float* __restrict__ dstR,
                     float* __restrict__ dst2)
{
    long long t = blockIdx.x;
    const float* xr = x   + t * DMODELC;
    const float* rr = res + t * DMODELC;
    float v[4];
    float s = 0.f, sq = 0.f;
    #pragma unroll
    for (int r = 0; r < 4; r++) {
        int d = threadIdx.x + 256 * r;
        float u = xr[d] + rr[d];
        v[r] = u; s += u; sq += u * u;
    }
    float sum  = block_reduce_sum(s);
    float sums = block_reduce_sum(sq);
    float mean = sum * (1.0f / 1024.0f);
    float var  = sums * (1.0f / 1024.0f) - mean * mean;
    float rstd = rsqrtf(var + 1e-5f);
    #pragma unroll
    for (int r = 0; r < 4; r++) {
        int d = threadIdx.x + 256 * r;
        float y = (v[r] - mean) * rstd * g[d] + bb[d];
        dst [t * DMODELC + d] = y;
        dstR[t * DMODELC + d] = tf32r(y);
        if (dst2) dst2[t * DMODELC + d] = y;
    }
}

// ------------------------------ host dispatch ------------------------------
template<int BN, bool TB, int EPI, bool RND, bool CVTA, bool CVTB>
static inline void launch_tg(const float* A, const float* B, float* C,
    const float* bias, int gx, int gy, int gz,
    int K, int lda, int ldb, int ldc,
    int batch2 = 1,
    long long sA1 = 0, long long sA2 = 0,
    long long sB1 = 0, long long sB2 = 0,
    long long sC1 = 0, long long sC2 = 0)
{
    const int A_ELE = 128 * 36;
    const int B_ELE = TB ? (BN * 36) : (32 * (BN + 4));
    int smem = (2 * A_ELE + 2 * B_ELE + 2048) * 4;
    cudaFuncSetAttribute(tgemm_k<BN, TB, EPI, RND, CVTA, CVTB>,
                         cudaFuncAttributeMaxDynamicSharedMemorySize, smem);
    tgemm_k<BN, TB, EPI, RND, CVTA, CVTB><<<dim3(gx, gy, gz), 256, smem>>>(
        A, B, C, bias, K, lda, ldb, ldc, batch2, sA1, sA2, sB1, sB2, sC1, sC2);
}

extern "C" void kernel_launch(void* const* d_in, const int* in_sizes, int n_in,
                              void* d_out, int out_size)
{
    const int*   data   = (const int*)  d_in[0];
    const int*   target = (const int*)  d_in[1];
    const float* memory = (const float*)d_in[2];
    const float* emb_W  = (const float*)d_in[3];
    const float* rwb    = (const float*)d_in[4];
    const float* rrb    = (const float*)d_in[5];
    const float* Wq     = (const float*)d_in[6];
    const float* Wkv    = (const float*)d_in[7];
    const float* Wr     = (const float*)d_in[8];
    const float* Wo     = (const float*)d_in[9];
    const float* W1     = (const float*)d_in[10];
    const float* b1     = (const float*)d_in[11];
    const float* W2     = (const float*)d_in[12];
    const float* b2     = (const float*)d_in[13];
    const float* ln1g   = (const float*)d_in[14];
    const float* ln1b   = (const float*)d_in[15];
    const float* ln2g   = (const float*)d_in[16];
    const float* ln2b   = (const float*)d_in[17];
    float* out = (float*)d_out;

    float *core, *coreR, *q, *qw, *qr, *kv, *rk, *pos, *scores, *bdp, *probs,
          *vec, *tmp, *h1, *pmax, *psum, *tgtl;
    bf *embb, *coreb;
    cudaGetSymbolAddress((void**)&core,   g_core);
    cudaGetSymbolAddress((void**)&coreR,  g_coreR);
    cudaGetSymbolAddress((void**)&q,      g_q);
    cudaGetSymbolAddress((void**)&qw,     g_qw);
    cudaGetSymbolAddress((void**)&qr,     g_qr);
    cudaGetSymbolAddress((void**)&kv,     g_kv);
    cudaGetSymbolAddress((void**)&rk,     g_rk);
    cudaGetSymbolAddress((void**)&pos,    g_pos);
    cudaGetSymbolAddress((void**)&scores, g_scores);
    cudaGetSymbolAddress((void**)&bdp,    g_bd);
    cudaGetSymbolAddress((void**)&probs,  g_probs);
    cudaGetSymbolAddress((void**)&vec,    g_vec);
    cudaGetSymbolAddress((void**)&tmp,    g_tmp);
    cudaGetSymbolAddress((void**)&h1,     g_h1);
    cudaGetSymbolAddress((void**)&pmax,   g_pmax);
    cudaGetSymbolAddress((void**)&psum,   g_psum);
    cudaGetSymbolAddress((void**)&tgtl,   g_tgt);
    cudaGetSymbolAddress((void**)&embb,   g_embb);
    cudaGetSymbolAddress((void**)&coreb,  g_coreb);

    const long long LSLOT = (long long)NT * DMODELC;
    float* mems_out = out + NT;

    embed_k<<<NT, 256>>>(data, emb_W, core, coreR, mems_out);
    pos_k<<<KLENC, 256>>>(pos);
    conv_k<<<(NTOKC * DMODELC) / 1024, 256>>>(emb_W, embb, NTOKC * DMODELC);

    for (int l = 0; l < NLAYERC; l++) {
        const float* Wq_l  = Wq  + (long long)l * DMODELC * DMODELC;
        const float* Wkv_l = Wkv + (long long)l * DMODELC * 2 * DMODELC;
        const float* Wr_l  = Wr  + (long long)l * DMODELC * DMODELC;
        const float* Wo_l  = Wo  + (long long)l * DMODELC * DMODELC;
        const float* W1_l  = W1  + (long long)l * DMODELC * DINNERC;
        const float* b1_l  = b1  + (long long)l * DINNERC;
        const float* W2_l  = W2  + (long long)l * DINNERC * DMODELC;
        const float* b2_l  = b2  + (long long)l * DMODELC;
        const float* mem_l = memory + (long long)l * LSLOT;

        // kv rows 0..4095 (memory tokens, unrounded A -> CVTA)
        launch_tg<128, false, 0, true, true, true>(mem_l, Wkv_l, kv, nullptr,
            2 * DMODELC / 128, 32, 1, DMODELC, DMODELC, 2 * DMODELC, 2 * DMODELC);
        // kv rows 4096..8191 (current tokens, coreR pre-rounded)
        launch_tg<128, false, 0, true, false, true>(coreR, Wkv_l,
            kv + (long long)NT * 2 * DMODELC, nullptr,
            2 * DMODELC / 128, 32, 1, DMODELC, DMODELC, 2 * DMODELC, 2 * DMODELC);

        // q = coreR @ Wq
        launch_tg<128, false, 0, false, false, true>(coreR, Wq_l, q, nullptr,
            DMODELC / 128, NT / 128, 1, DMODELC, DMODELC, DMODELC, DMODELC);
        qwqr_k<<<(NT * DMODELC) / 256, 256>>>(q, rwb, rrb, qw, qr);

        // r_k = pos @ Wr (rounded out)
        launch_tg<128, false, 0, true, false, true>(pos, Wr_l, rk, nullptr,
            DMODELC / 128, KLENC / 128, 1, DMODELC, DMODELC, DMODELC, DMODELC);

        // AC[b,n] = qw[512,64] @ k^T  (cvt-free: both operands pre-rounded)
        launch_tg<128, true, 0, false, false, false>(qw, kv, scores, nullptr,
            KLENC / 128, QLENC / 128, BSZC * NHEADC,
            DHEADC, BSZC * DMODELC, BSZC * 2 * DMODELC, KLENC,
            NHEADC,
            DMODELC, DHEADC,
            2 * DMODELC, DHEADC,
            (long long)NHEADC * QLENC * KLENC, (long long)QLENC * KLENC);

        // BD_raw[n] = qr @ rk^T  (cvt-free)
        launch_tg<128, true, 0, false, false, false>(qr, rk, bdp, nullptr,
            KLENC / 128, NT / 128, NHEADC,
            DHEADC, DMODELC, DMODELC, KLENC,
            NHEADC,
            0, DHEADC, 0, DHEADC, 0, (long long)NT * KLENC);

        softmax_k<<<dim3(QLENC, BSZC * NHEADC), 256>>>(scores, bdp, probs);

        // vec[b,n] = probs @ v  (BN=64, cvt-free, rounded out)
        launch_tg<64, false, 0, true, false, false>(probs, kv + DMODELC, vec, nullptr,
            1, QLENC / 128, BSZC * NHEADC,
            KLENC, KLENC, BSZC * 2 * DMODELC, BSZC * DMODELC,
            NHEADC,
            (long long)NHEADC * QLENC * KLENC, (long long)QLENC * KLENC,
            2 * DMODELC, DHEADC,
            DMODELC, DHEADC);

        // attn_out = vec @ Wo
        launch_tg<128, false, 0, false, false, true>(vec, Wo_l, tmp, nullptr,
            DMODELC / 128, NT / 128, 1, DMODELC, DMODELC, DMODELC, DMODELC);

        ln_k<<<NT, 256>>>(core, tmp, ln1g + l * DMODELC, ln1b + l * DMODELC,
                          core, coreR, nullptr);

        // h1 = relu(coreR @ W1 + b1) (rounded out)
        launch_tg<128, false, 2, true, false, true>(coreR, W1_l, h1, b1_l,
            DINNERC / 128, NT / 128, 1, DMODELC, DMODELC, DINNERC, DINNERC);

        // ff = h1 @ W2 + b2
        launch_tg<128, false, 1, false, false, true>(h1, W2_l, tmp, b2_l,
            DMODELC / 128, NT / 128, 1, DINNERC, DINNERC, DMODELC, DMODELC);

        float* memout = (l < NLAYERC - 1) ? (mems_out + (long long)(l + 1) * LSLOT)
                                          : nullptr;
        ln_k<<<NT, 256>>>(core, tmp, ln2g + l * DMODELC, ln2b + l * DMODELC,
                          core, coreR, memout);
    }

    // logits GEMM fused with per-tile log-softmax partials, then reduce
    conv_k<<<(NT * DMODELC) / 1024, 256>>>(core, coreb, NT * DMODELC);
    bgemm_loss_k<<<dim3(NTILE_V, NT / 128, 1), 256>>>(
        coreb, embb, target, pmax, psum, tgtl, DMODELC, DMODELC, DMODELC);
    loss_red_k<<<NT, 128>>>(pmax, psum, tgtl, out);
}

// round 10
// speedup vs baseline: 1.1418x; 1.0015x over previous
#include <cuda_runtime.h>
#include <cuda_bf16.h>
#include <mma.h>
#include <math.h>

using namespace nvcuda;

#define QLENC   512
#define KLENC   1024
#define BSZC    8
#define NHEADC  16
#define DHEADC  64
#define DMODELC 1024
#define DINNERC 4096
#define NTOKC   32000
#define NLAYERC 6
#define NT      4096
#define KT      8192
#define NTILE_V (NTOKC / 128)   // 250 logits column tiles

typedef __nv_bfloat16 bf;

__device__ __forceinline__ float tf32r(float x) {
    float r;
    asm("cvt.rna.tf32.f32 %0, %1;" : "=f"(r) : "f"(x));
    return r;
}

// ------------------------- scratch (device globals) ------------------------
__device__ float g_core [NT * DMODELC];
__device__ float g_coreR[NT * DMODELC];
__device__ float g_q  [NT * DMODELC];
__device__ float g_qw [NT * DMODELC];
__device__ float g_qr [NT * DMODELC];
__device__ float g_kv [KT * 2 * DMODELC];
__device__ float g_rk [KLENC * DMODELC];
__device__ float g_pos[KLENC * DMODELC];
__device__ float g_scores[67108864];   // [b*16+n][512][1024]
__device__ float g_bd    [67108864];   // [n][4096][1024]
__device__ float g_probs [67108864];
__device__ float g_vec[NT * DMODELC];
__device__ float g_tmp[NT * DMODELC];
__device__ float g_h1 [NT * DINNERC];
__device__ bf    g_embb [NTOKC * DMODELC];
__device__ bf    g_coreb[NT * DMODELC];
__device__ float g_pmax[NT * NTILE_V];
__device__ float g_psum[NT * NTILE_V];
__device__ float g_tgt [NT];

// ------------------------------ cp.async helpers ---------------------------
__device__ __forceinline__ void cp16(void* dst, const void* src) {
    unsigned d = (unsigned)__cvta_generic_to_shared(dst);
    asm volatile("cp.async.cg.shared.global [%0], [%1], 16;\n" :: "r"(d), "l"(src));
}
__device__ __forceinline__ void cp_commit() { asm volatile("cp.async.commit_group;\n"); }
__device__ __forceinline__ void cp_wait0()  { asm volatile("cp.async.wait_group 0;\n"); }

// ------------------------------- reductions --------------------------------
__device__ __forceinline__ float block_reduce_max(float v) {
    __shared__ float sd[256];
    int tid = threadIdx.x;
    sd[tid] = v; __syncthreads();
    #pragma unroll
    for (int s = 128; s > 0; s >>= 1) {
        if (tid < s) sd[tid] = fmaxf(sd[tid], sd[tid + s]);
        __syncthreads();
    }
    float r = sd[0]; __syncthreads();
    return r;
}
__device__ __forceinline__ float block_reduce_sum(float v) {
    __shared__ float sd[256];
    int tid = threadIdx.x;
    sd[tid] = v; __syncthreads();
    #pragma unroll
    for (int s = 128; s > 0; s >>= 1) {
        if (tid < s) sd[tid] += sd[tid + s];
        __syncthreads();
    }
    float r = sd[0]; __syncthreads();
    return r;
}

// --------------------- tf32 double-buffered wmma GEMM ----------------------
template<int BN, bool TB, int EPI, bool RND, bool CVTA, bool CVTB>
__global__ void __launch_bounds__(256) tgemm_k(
    const float* __restrict__ A, const float* __restrict__ B,
    float* __restrict__ C, const float* __restrict__ bias,
    int K, int lda, int ldb, int ldc,
    int batch2,
    long long sA1, long long sA2, long long sB1, long long sB2,
    long long sC1, long long sC2)
{
    constexpr int WARPS_N = BN / 32;
    constexpr int WARPS_M = 8 / WARPS_N;
    constexpr int MI = 128 / (WARPS_M * 16);
    constexpr int NI = 2;
    constexpr int A_LD  = 36;
    constexpr int A_ELE = 128 * A_LD;
    constexpr int B_LD  = TB ? 36 : (BN + 4);
    constexpr int B_ELE = TB ? (BN * 36) : (32 * (BN + 4));

    int z = blockIdx.z;
    int z1 = z / batch2, z2 = z - z1 * batch2;
    A += z1 * sA1 + z2 * sA2;
    B += z1 * sB1 + z2 * sB2;
    C += z1 * sC1 + z2 * sC2;

    extern __shared__ float smem[];
    float* sA[2] = { smem, smem + A_ELE };
    float* sB[2] = { smem + 2 * A_ELE, smem + 2 * A_ELE + B_ELE };
    float* stage = smem + 2 * A_ELE + 2 * B_ELE;

    const int tid  = threadIdx.x;
    const int m0   = blockIdx.y * 128, n0 = blockIdx.x * BN;
    const int warp = tid >> 5, lane = tid & 31;
    const int wm   = warp / WARPS_N, wn = warp % WARPS_N;
    const int wmB  = wm * MI * 16, wnB = wn * 32;

    wmma::fragment<wmma::accumulator, 16, 16, 8, float> acc[MI][NI];
    #pragma unroll
    for (int i = 0; i < MI; i++)
        #pragma unroll
        for (int j = 0; j < NI; j++)
            wmma::fill_fragment(acc[i][j], 0.f);

    auto loadA = [&](int buf, int k0) {
        #pragma unroll
        for (int p = 0; p < 4; p++) {
            int row = p * 32 + (tid >> 3), col = (tid & 7) * 4;
            cp16(&sA[buf][row * A_LD + col],
                 A + (long long)(m0 + row) * lda + k0 + col);
        }
    };
    auto loadB = [&](int buf, int k0) {
        if (TB) {
            #pragma unroll
            for (int p = 0; p < BN / 32; p++) {
                int row = p * 32 + (tid >> 3), col = (tid & 7) * 4;
                cp16(&sB[buf][row * B_LD + col],
                     B + (long long)(n0 + row) * ldb + k0 + col);
            }
        } else {
            constexpr int TPR = BN / 4;
            constexpr int RPP = 256 / TPR;
            #pragma unroll
            for (int p = 0; p < 32 / RPP; p++) {
                int row = p * RPP + tid / TPR;
                int col = (tid % TPR) * 4;
                cp16(&sB[buf][row * B_LD + col],
                     B + (long long)(k0 + row) * ldb + n0 + col);
            }
        }
    };
    auto compute = [&](int buf) {
        #pragma unroll
        for (int kk = 0; kk < 4; kk++) {
            wmma::fragment<wmma::matrix_a, 16, 16, 8, wmma::precision::tf32,
                           wmma::row_major> af[MI];
            #pragma unroll
            for (int i = 0; i < MI; i++) {
                wmma::load_matrix_sync(af[i],
                    &sA[buf][(wmB + i * 16) * A_LD + kk * 8], A_LD);
                if (CVTA) {
                    #pragma unroll
                    for (int e = 0; e < af[i].num_elements; e++)
                        af[i].x[e] = wmma::__float_to_tf32(af[i].x[e]);
                }
            }
            #pragma unroll
            for (int j = 0; j < NI; j++) {
                if (TB) {
                    wmma::fragment<wmma::matrix_b, 16, 16, 8, wmma::precision::tf32,
                                   wmma::col_major> bfg;
                    wmma::load_matrix_sync(bfg,
                        &sB[buf][(wnB + j * 16) * B_LD + kk * 8], B_LD);
                    if (CVTB) {
                        #pragma unroll
                        for (int e = 0; e < bfg.num_elements; e++)
                            bfg.x[e] = wmma::__float_to_tf32(bfg.x[e]);
                    }
                    #pragma unroll
                    for (int i = 0; i < MI; i++)
                        wmma::mma_sync(acc[i][j], af[i], bfg, acc[i][j]);
                } else {
                    wmma::fragment<wmma::matrix_b, 16, 16, 8, wmma::precision::tf32,
                                   wmma::row_major> bfg;
                    wmma::load_matrix_sync(bfg,
                        &sB[buf][(kk * 8) * B_LD + wnB + j * 16], B_LD);
                    if (CVTB) {
                        #pragma unroll
                        for (int e = 0; e < bfg.num_elements; e++)
                            bfg.x[e] = wmma::__float_to_tf32(bfg.x[e]);
                    }
                    #pragma unroll
                    for (int i = 0; i < MI; i++)
                        wmma::mma_sync(acc[i][j], af[i], bfg, acc[i][j]);
                }
            }
        }
    };

    int buf = 0;
    loadA(0, 0); loadB(0, 0); cp_commit();
    for (int k0 = 0; k0 < K; k0 += 32) {
        cp_wait0();
        __syncthreads();
        int nk = k0 + 32;
        if (nk < K) { loadA(buf ^ 1, nk); loadB(buf ^ 1, nk); }
        cp_commit();
        compute(buf);
        buf ^= 1;
    }

    if (EPI == 0 && !RND) {
        #pragma unroll
        for (int i = 0; i < MI; i++)
            #pragma unroll
            for (int j = 0; j < NI; j++) {
                int row0 = m0 + wmB + i * 16;
                int col0 = n0 + wnB + j * 16;
                wmma::store_matrix_sync(C + (long long)row0 * ldc + col0,
                                        acc[i][j], ldc, wmma::mem_row_major);
            }
    } else {
        float* st = stage + warp * 256;
        #pragma unroll
        for (int i = 0; i < MI; i++)
            #pragma unroll
            for (int j = 0; j < NI; j++) {
                int row0 = m0 + wmB + i * 16;
                int col0 = n0 + wnB + j * 16;
                wmma::store_matrix_sync(st, acc[i][j], 16, wmma::mem_row_major);
                __syncwarp();
                #pragma unroll
                for (int e = 0; e < 8; e++) {
                    int idx = lane * 8 + e;
                    int r = idx >> 4, c = idx & 15;
                    float v = st[idx];
                    int col = col0 + c;
                    if (EPI >= 1) v += bias[col];
                    if (EPI == 2) v = fmaxf(v, 0.f);
                    if (RND)      v = tf32r(v);
                    C[(long long)(row0 + r) * ldc + col] = v;
                }
                __syncwarp();
            }
    }
}

// ---------- bf16 logits GEMM with fused per-tile log-softmax partials ------
__global__ void __launch_bounds__(256) bgemm_loss_k(
    const bf* __restrict__ A, const bf* __restrict__ B,
    const int* __restrict__ target,
    float* __restrict__ pmax_out, float* __restrict__ psum_out,
    float* __restrict__ tgtlog,
    int K, int lda, int ldb)
{
    __shared__ bf sA[2][128 * 40];
    __shared__ bf sB[2][128 * 40];
    __shared__ float sPmB[128][4];
    __shared__ float sPsB[128][4];
    __shared__ float sMB[128];
    __shared__ float sStageB[8][256];

    const int tid  = threadIdx.x;
    const int m0   = blockIdx.y * 128, n0 = blockIdx.x * 128;
    const int warp = tid >> 5, lane = tid & 31;
    const int wm   = warp >> 2, wn = warp & 3;
    const int wmB  = wm * 64, wnB = wn * 32;

    wmma::fragment<wmma::accumulator, 16, 16, 16, float> acc[4][2];
    #pragma unroll
    for (int i = 0; i < 4; i++)
        #pragma unroll
        for (int j = 0; j < 2; j++)
            wmma::fill_fragment(acc[i][j], 0.f);

    auto loadAB = [&](int buf, int k0) {
        #pragma unroll
        for (int p = 0; p < 2; p++) {
            int row = p * 64 + (tid >> 2), col = (tid & 3) * 8;
            cp16(&sA[buf][row * 40 + col],
                 A + (long long)(m0 + row) * lda + k0 + col);
            cp16(&sB[buf][row * 40 + col],
                 B + (long long)(n0 + row) * ldb + k0 + col);
        }
    };
    auto compute = [&](int buf) {
        #pragma unroll
        for (int kk = 0; kk < 2; kk++) {
            wmma::fragment<wmma::matrix_a, 16, 16, 16, bf, wmma::row_major> af[4];
            #pragma unroll
            for (int i = 0; i < 4; i++)
                wmma::load_matrix_sync(af[i], &sA[buf][(wmB + i * 16) * 40 + kk * 16], 40);
            #pragma unroll
            for (int j = 0; j < 2; j++) {
                wmma::fragment<wmma::matrix_b, 16, 16, 16, bf, wmma::col_major> bfg;
                wmma::load_matrix_sync(bfg, &sB[buf][(wnB + j * 16) * 40 + kk * 16], 40);
                #pragma unroll
                for (int i = 0; i < 4; i++)
                    wmma::mma_sync(acc[i][j], af[i], bfg, acc[i][j]);
            }
        }
    };

    int buf = 0;
    loadAB(0, 0); cp_commit();
    for (int k0 = 0; k0 < K; k0 += 32) {
        cp_wait0();
        __syncthreads();
        int nk = k0 + 32;
        if (nk < K) loadAB(buf ^ 1, nk);
        cp_commit();
        compute(buf);
        buf ^= 1;
    }

    float* st = sStageB[warp];
    #pragma unroll
    for (int i = 0; i < 4; i++) {
        float mx = -1e30f;
        #pragma unroll
        for (int j = 0; j < 2; j++) {
            wmma::store_matrix_sync(st, acc[i][j], 16, wmma::mem_row_major);
            __syncwarp();
            if (lane < 16) {
                #pragma unroll
                for (int c = 0; c < 16; c++) mx = fmaxf(mx, st[lane * 16 + c]);
            }
            __syncwarp();
        }
        if (lane < 16) sPmB[wmB + i * 16 + lane][wn] = mx;
    }
    __syncthreads();
    if (tid < 128)
        sMB[tid] = fmaxf(fmaxf(sPmB[tid][0], sPmB[tid][1]),
                         fmaxf(sPmB[tid][2], sPmB[tid][3]));
    __syncthreads();
    #pragma unroll
    for (int i = 0; i < 4; i++) {
        int rloc = wmB + i * 16 + (lane & 15);
        float m = sMB[rloc];
        int t = m0 + rloc;
        int tg = (lane < 16) ? target[t] : -1;
        float sme = 0.f;
        #pragma unroll
        for (int j = 0; j < 2; j++) {
            wmma::store_matrix_sync(st, acc[i][j], 16, wmma::mem_row_major);
            __syncwarp();
            if (lane < 16) {
                #pragma unroll
                for (int c = 0; c < 16; c++) {
                    float x = st[lane * 16 + c];
                    sme += expf(x - m);
                    int col = n0 + wnB + j * 16 + c;
                    if (col == tg) tgtlog[t] = x;
                }
            }
            __syncwarp();
        }
        if (lane < 16) sPsB[rloc][wn] = sme;
    }
    __syncthreads();
    if (tid < 128) {
        float s = sPsB[tid][0] + sPsB[tid][1] + sPsB[tid][2] + sPsB[tid][3];
        long long idx = (long long)(m0 + tid) * NTILE_V + blockIdx.x;
        pmax_out[idx] = sMB[tid];
        psum_out[idx] = s;
    }
}

__global__ void loss_red_k(const float* __restrict__ pmax, const float* __restrict__ psum,
                           const float* __restrict__ tgt, float* __restrict__ out)
{
    int t = blockIdx.x;
    const float* pm = pmax + (long long)t * NTILE_V;
    const float* ps = psum + (long long)t * NTILE_V;
    __shared__ float sd[128];
    int tid = threadIdx.x;
    float m = -1e30f;
    for (int j = tid; j < NTILE_V; j += 128) m = fmaxf(m, pm[j]);
    sd[tid] = m; __syncthreads();
    #pragma unroll
    for (int s = 64; s > 0; s >>= 1) {
        if (tid < s) sd[tid] = fmaxf(sd[tid], sd[tid + s]);
        __syncthreads();
    }
    m = sd[0]; __syncthreads();
    float su = 0.f;
    for (int j = tid; j < NTILE_V; j += 128) su += ps[j] * expf(pm[j] - m);
    sd[tid] = su; __syncthreads();
    #pragma unroll
    for (int s = 64; s > 0; s >>= 1) {
        if (tid < s) sd[tid] += sd[tid + s];
        __syncthreads();
    }
    if (tid == 0) out[t] = -(tgt[t] - m - logf(sd[0]));
}

// ------------------------------ small kernels ------------------------------
__global__ void conv_k(const float* __restrict__ src, bf* __restrict__ dst, int n)
{
    int i = (blockIdx.x * 256 + threadIdx.x) * 4;
    if (i < n) {
        float4 v = *(const float4*)(src + i);
        dst[i + 0] = __float2bfloat16_rn(v.x);
        dst[i + 1] = __float2bfloat16_rn(v.y);
        dst[i + 2] = __float2bfloat16_rn(v.z);
        dst[i + 3] = __float2bfloat16_rn(v.w);
    }
}

__global__ void embed_k(const int* __restrict__ data, const float* __restrict__ emb,
                        float* __restrict__ core, float* __restrict__ coreR,
                        float* __restrict__ memout)
{
    int t = blockIdx.x;
    int tok = data[t];
    const float* src = emb + (long long)tok * DMODELC;
    #pragma unroll
    for (int r = 0; r < 4; r++) {
        int d = threadIdx.x + 256 * r;
        float v = src[d];
        core  [(long long)t * DMODELC + d] = v;
        coreR [(long long)t * DMODELC + d] = tf32r(v);
        memout[(long long)t * DMODELC + d] = v;
    }
}

__global__ void pos_k(float* __restrict__ pos)
{
    int k = blockIdx.x;
    float p = (float)(KLENC - 1 - k);
    #pragma unroll
    for (int r = 0; r < 4; r++) {
        int c = threadIdx.x + 256 * r;
        int j = (c < 512) ? c : (c - 512);
        float invf = 1.0f / powf(10000.0f, (2.0f * (float)j) / 1024.0f);
        float ang = p * invf;
        float v = (c < 512) ? sinf(ang) : cosf(ang);
        pos[(long long)k * DMODELC + c] = tf32r(v);
    }
}

__global__ void qwqr_k(const float* __restrict__ q, const float* __restrict__ rwb,
                       const float* __restrict__ rrb,
                       float* __restrict__ qw, float* __restrict__ qr)
{
    long long idx = (long long)blockIdx.x * 256 + threadIdx.x;
    int c = (int)(idx & 1023);
    float v = q[idx];
    qw[idx] = tf32r(v + rwb[c]);
    qr[idx] = tf32r(v + rrb[c]);
}

__global__ void softmax_k(const float* __restrict__ scores, const float* __restrict__ bd,
                          float* __restrict__ probs)
{
    int i  = blockIdx.x;
    int bn = blockIdx.y;
    int b = bn >> 4, n = bn & 15;
    const float* ac = scores + (long long)bn * (QLENC * KLENC) + (long long)i * KLENC;
    float* pr = probs + (long long)bn * (QLENC * KLENC) + (long long)i * KLENC;
    const float* bdr = bd + (long long)n * ((long long)NT * KLENC)
                          + (long long)(i * BSZC + b) * KLENC;
    int shift = QLENC - 1 - i;
    int lim = i + 512;

    float vals[4];
    float lmax = -1e30f;
    #pragma unroll
    for (int r = 0; r < 4; r++) {
        int j = threadIdx.x + 256 * r;
        float v = -1e30f;
        if (j <= lim) v = (ac[j] + bdr[j + shift]) * 0.125f;
        vals[r] = v;
        lmax = fmaxf(lmax, v);
    }
    float rmax = block_reduce_max(lmax);
    float lsum = 0.f;
    #pragma unroll
    for (int r = 0; r < 4; r++) {
        float e = expf(vals[r] - rmax);
        vals[r] = e;
        lsum += e;
    }
    float rsum = block_reduce_sum(lsum);
    float inv = 1.0f / rsum;
    #pragma unroll
    for (int r = 0; r < 4; r++) {
        int j = threadIdx.x + 256 * r;
        pr[j] = tf32r(vals[r] * inv);
    }
}

__global__ void ln_k(const float* __restrict__ x, const float* __restrict__ res,
                     const float* __restrict__ g, const float* __restrict__ bb,
                     float* __restrict__ dst, float* __restrict__ dstR,
                     float* __restrict__ dst2)
{
    long long t = blockIdx.x;
    const float* xr = x   + t * DMODELC;
    const float* rr = res + t * DMODELC;
    float v[4];
    float s = 0.f, sq = 0.f;
    #pragma unroll
    for (int r = 0; r < 4; r++) {
        int d = threadIdx.x + 256 * r;
        float u = xr[d] + rr[d];
        v[r] = u; s += u; sq += u * u;
    }
    float sum  = block_reduce_sum(s);
    float sums = block_reduce_sum(sq);
    float mean = sum * (1.0f / 1024.0f);
    float var  = sums * (1.0f / 1024.0f) - mean * mean;
    float rstd = rsqrtf(var + 1e-5f);
    #pragma unroll
    for (int r = 0; r < 4; r++) {
        int d = threadIdx.x + 256 * r;
        float y = (v[r] - mean) * rstd * g[d] + bb[d];
        dst [t * DMODELC + d] = y;
        dstR[t * DMODELC + d] = tf32r(y);
        if (dst2) dst2[t * DMODELC + d] = y;
    }
}

// ------------------------------ host dispatch ------------------------------
template<int BN, bool TB, int EPI, bool RND, bool CVTA, bool CVTB>
static inline void launch_tg(const float* A, const float* B, float* C,
    const float* bias, int gx, int gy, int gz,
    int K, int lda, int ldb, int ldc,
    int batch2 = 1,
    long long sA1 = 0, long long sA2 = 0,
    long long sB1 = 0, long long sB2 = 0,
    long long sC1 = 0, long long sC2 = 0)
{
    const int A_ELE = 128 * 36;
    const int B_ELE = TB ? (BN * 36) : (32 * (BN + 4));
    int smem = (2 * A_ELE + 2 * B_ELE + 2048) * 4;
    cudaFuncSetAttribute(tgemm_k<BN, TB, EPI, RND, CVTA, CVTB>,
                         cudaFuncAttributeMaxDynamicSharedMemorySize, smem);
    tgemm_k<BN, TB, EPI, RND, CVTA, CVTB><<<dim3(gx, gy, gz), 256, smem>>>(
        A, B, C, bias, K, lda, ldb, ldc, batch2, sA1, sA2, sB1, sB2, sC1, sC2);
}

extern "C" void kernel_launch(void* const* d_in, const int* in_sizes, int n_in,
                              void* d_out, int out_size)
{
    const int*   data   = (const int*)  d_in[0];
    const int*   target = (const int*)  d_in[1];
    const float* memory = (const float*)d_in[2];
    const float* emb_W  = (const float*)d_in[3];
    const float* rwb    = (const float*)d_in[4];
    const float* rrb    = (const float*)d_in[5];
    const float* Wq     = (const float*)d_in[6];
    const float* Wkv    = (const float*)d_in[7];
    const float* Wr     = (const float*)d_in[8];
    const float* Wo     = (const float*)d_in[9];
    const float* W1     = (const float*)d_in[10];
    const float* b1     = (const float*)d_in[11];
    const float* W2     = (const float*)d_in[12];
    const float* b2     = (const float*)d_in[13];
    const float* ln1g   = (const float*)d_in[14];
    const float* ln1b   = (const float*)d_in[15];
    const float* ln2g   = (const float*)d_in[16];
    const float* ln2b   = (const float*)d_in[17];
    float* out = (float*)d_out;

    float *core, *coreR, *q, *qw, *qr, *kv, *rk, *pos, *scores, *bdp, *probs,
          *vec, *tmp, *h1, *pmax, *psum, *tgtl;
    bf *embb, *coreb;
    cudaGetSymbolAddress((void**)&core,   g_core);
    cudaGetSymbolAddress((void**)&coreR,  g_coreR);
    cudaGetSymbolAddress((void**)&q,      g_q);
    cudaGetSymbolAddress((void**)&qw,     g_qw);
    cudaGetSymbolAddress((void**)&qr,     g_qr);
    cudaGetSymbolAddress((void**)&kv,     g_kv);
    cudaGetSymbolAddress((void**)&rk,     g_rk);
    cudaGetSymbolAddress((void**)&pos,    g_pos);
    cudaGetSymbolAddress((void**)&scores, g_scores);
    cudaGetSymbolAddress((void**)&bdp,    g_bd);
    cudaGetSymbolAddress((void**)&probs,  g_probs);
    cudaGetSymbolAddress((void**)&vec,    g_vec);
    cudaGetSymbolAddress((void**)&tmp,    g_tmp);
    cudaGetSymbolAddress((void**)&h1,     g_h1);
    cudaGetSymbolAddress((void**)&pmax,   g_pmax);
    cudaGetSymbolAddress((void**)&psum,   g_psum);
    cudaGetSymbolAddress((void**)&tgtl,   g_tgt);
    cudaGetSymbolAddress((void**)&embb,   g_embb);
    cudaGetSymbolAddress((void**)&coreb,  g_coreb);

    const long long LSLOT = (long long)NT * DMODELC;
    float* mems_out = out + NT;

    embed_k<<<NT, 256>>>(data, emb_W, core, coreR, mems_out);
    pos_k<<<KLENC, 256>>>(pos);
    conv_k<<<(NTOKC * DMODELC) / 1024, 256>>>(emb_W, embb, NTOKC * DMODELC);

    for (int l = 0; l < NLAYERC; l++) {
        const float* Wq_l  = Wq  + (long long)l * DMODELC * DMODELC;
        const float* Wkv_l = Wkv + (long long)l * DMODELC * 2 * DMODELC;
        const float* Wr_l  = Wr  + (long long)l * DMODELC * DMODELC;
        const float* Wo_l  = Wo  + (long long)l * DMODELC * DMODELC;
        const float* W1_l  = W1  + (long long)l * DMODELC * DINNERC;
        const float* b1_l  = b1  + (long long)l * DINNERC;
        const float* W2_l  = W2  + (long long)l * DINNERC * DMODELC;
        const float* b2_l  = b2  + (long long)l * DMODELC;
        const float* mem_l = memory + (long long)l * LSLOT;

        // kv rows 0..4095 (memory tokens, unrounded A -> CVTA)
        launch_tg<128, false, 0, true, true, true>(mem_l, Wkv_l, kv, nullptr,
            2 * DMODELC / 128, 32, 1, DMODELC, DMODELC, 2 * DMODELC, 2 * DMODELC);
        // kv rows 4096..8191 (current tokens, coreR pre-rounded)
        launch_tg<128, false, 0, true, false, true>(coreR, Wkv_l,
            kv + (long long)NT * 2 * DMODELC, nullptr,
            2 * DMODELC / 128, 32, 1, DMODELC, DMODELC, 2 * DMODELC, 2 * DMODELC);

        // q = coreR @ Wq
        launch_tg<128, false, 0, false, false, true>(coreR, Wq_l, q, nullptr,
            DMODELC / 128, NT / 128, 1, DMODELC, DMODELC, DMODELC, DMODELC);
        qwqr_k<<<(NT * DMODELC) / 256, 256>>>(q, rwb, rrb, qw, qr);

        // r_k = pos @ Wr (rounded out)
        launch_tg<128, false, 0, true, false, true>(pos, Wr_l, rk, nullptr,
            DMODELC / 128, KLENC / 128, 1, DMODELC, DMODELC, DMODELC, DMODELC);

        // AC[b,n] = qw[512,64] @ k^T  (cvt-free: both operands pre-rounded)
        launch_tg<128, true, 0, false, false, false>(qw, kv, scores, nullptr,
            KLENC / 128, QLENC / 128, BSZC * NHEADC,
            DHEADC, BSZC * DMODELC, BSZC * 2 * DMODELC, KLENC,
            NHEADC,
            DMODELC, DHEADC,
            2 * DMODELC, DHEADC,
            (long long)NHEADC * QLENC * KLENC, (long long)QLENC * KLENC);

        // BD_raw[n] = qr @ rk^T  (cvt-free)
        launch_tg<128, true, 0, false, false, false>(qr, rk, bdp, nullptr,
            KLENC / 128, NT / 128, NHEADC,
            DHEADC, DMODELC, DMODELC, KLENC,
            NHEADC,
            0, DHEADC, 0, DHEADC, 0, (long long)NT * KLENC);

        softmax_k<<<dim3(QLENC, BSZC * NHEADC), 256>>>(scores, bdp, probs);

        // vec[b,n] = probs @ v  (BN=64, cvt-free, rounded out)
        launch_tg<64, false, 0, true, false, false>(probs, kv + DMODELC, vec, nullptr,
            1, QLENC / 128, BSZC * NHEADC,
            KLENC, KLENC, BSZC * 2 * DMODELC, BSZC * DMODELC,
            NHEADC,
            (long long)NHEADC * QLENC * KLENC, (long long)QLENC * KLENC,
            2 * DMODELC, DHEADC,
            DMODELC, DHEADC);

        // attn_out = vec @ Wo
        launch_tg<128, false, 0, false, false, true>(vec, Wo_l, tmp, nullptr,
            DMODELC / 128, NT / 128, 1, DMODELC, DMODELC, DMODELC, DMODELC);

        ln_k<<<NT, 256>>>(core, tmp, ln1g + l * DMODELC, ln1b + l * DMODELC,
                          core, coreR, nullptr);

        // h1 = relu(coreR @ W1 + b1) (rounded out)
        launch_tg<128, false, 2, true, false, true>(coreR, W1_l, h1, b1_l,
            DINNERC / 128, NT / 128, 1, DMODELC, DMODELC, DINNERC, DINNERC);

        // ff = h1 @ W2 + b2
        launch_tg<128, false, 1, false, false, true>(h1, W2_l, tmp, b2_l,
            DMODELC / 128, NT / 128, 1, DINNERC, DINNERC, DMODELC, DMODELC);

        float* memout = (l < NLAYERC - 1) ? (mems_out + (long long)(l + 1) * LSLOT)
                                          : nullptr;
        ln_k<<<NT, 256>>>(core, tmp, ln2g + l * DMODELC, ln2b + l * DMODELC,
                          core, coreR, memout);
    }

    // logits GEMM fused with per-tile log-softmax partials, then reduce
    conv_k<<<(NT * DMODELC) / 1024, 256>>>(core, coreb, NT * DMODELC);
    bgemm_loss_k<<<dim3(NTILE_V, NT / 128, 1), 256>>>(
        coreb, embb, target, pmax, psum, tgtl, DMODELC, DMODELC, DMODELC);
    loss_red_k<<<NT, 128>>>(pmax, psum, tgtl, out);
}

// round 16
// speedup vs baseline: 2.3499x; 2.0580x over previous
#include <cuda_runtime.h>
#include <cuda_fp16.h>
#include <cuda_bf16.h>
#include <mma.h>
#include <math.h>

using namespace nvcuda;

#define QLENC   512
#define KLENC   1024
#define BSZC    8
#define NHEADC  16
#define DHEADC  64
#define DMODELC 1024
#define DINNERC 4096
#define NTOKC   32000
#define NLAYERC 6
#define NT      4096
#define KT      8192
#define NTILE_V (NTOKC / 128)

typedef __half hf;
typedef __nv_bfloat16 bf;

// ------------------------- scratch (device globals) ------------------------
__device__ float g_core [NT * DMODELC];
__device__ hf    g_coreH[NT * DMODELC];
__device__ hf    g_memH [NT * DMODELC];
__device__ float g_q  [NT * DMODELC];
__device__ hf    g_qwH[NT * DMODELC];
__device__ hf    g_qrH[NT * DMODELC];
__device__ hf    g_kvH[KT * 2 * DMODELC];
__device__ hf    g_rkH[KLENC * DMODELC];
__device__ hf    g_posH[KLENC * DMODELC];
__device__ float g_scores[67108864];
__device__ float g_bd    [67108864];
__device__ hf    g_probsH[67108864];
__device__ hf    g_vecH[NT * DMODELC];
__device__ float g_tmp[NT * DMODELC];
__device__ hf    g_h1H[NT * DINNERC];
__device__ bf    g_embb [NTOKC * DMODELC];
__device__ bf    g_coreb[NT * DMODELC];
__device__ float g_pmax[NT * NTILE_V];
__device__ float g_psum[NT * NTILE_V];
__device__ float g_tgt [NT];
// fp16 weights (layout [K,N] as given)
__device__ hf g_WqH [NLAYERC * DMODELC * DMODELC];
__device__ hf g_WkvH[NLAYERC * DMODELC * 2 * DMODELC];
__device__ hf g_WrH [NLAYERC * DMODELC * DMODELC];
__device__ hf g_WoH [NLAYERC * DMODELC * DMODELC];
__device__ hf g_W1H [NLAYERC * DMODELC * DINNERC];
__device__ hf g_W2H [NLAYERC * DINNERC * DMODELC];

// ------------------------------ cp.async helpers ---------------------------
__device__ __forceinline__ void cp16(void* dst, const void* src) {
    unsigned d = (unsigned)__cvta_generic_to_shared(dst);
    asm volatile("cp.async.cg.shared.global [%0], [%1], 16;\n" :: "r"(d), "l"(src));
}
__device__ __forceinline__ void cp_commit() { asm volatile("cp.async.commit_group;\n"); }

// ------------------------------- reductions --------------------------------
__device__ __forceinline__ float block_reduce_max(float v) {
    __shared__ float sd[256];
    int tid = threadIdx.x;
    sd[tid] = v; __syncthreads();
    #pragma unroll
    for (int s = 128; s > 0; s >>= 1) {
        if (tid < s) sd[tid] = fmaxf(sd[tid], sd[tid + s]);
        __syncthreads();
    }
    float r = sd[0]; __syncthreads();
    return r;
}
__device__ __forceinline__ float block_reduce_sum(float v) {
    __shared__ float sd[256];
    int tid = threadIdx.x;
    sd[tid] = v; __syncthreads();
    #pragma unroll
    for (int s = 128; s > 0; s >>= 1) {
        if (tid < s) sd[tid] += sd[tid + s];
        __syncthreads();
    }
    float r = sd[0]; __syncthreads();
    return r;
}

// ------------------- fp16 double-buffered wmma GEMM ------------------------
// C[128*gy, BN*gx] = A[M,K]*op(B). A,B half. TB: B stored [N,K] (B^T).
// EPI: 0 none, 1 +bias, 2 +bias+relu. OUTH: write half, else fp32.
// Batched via z: z1=z/batch2, z2=z%batch2; strides in elements.
template<int BN, bool TB, int EPI, bool OUTH>
__global__ void __launch_bounds__(256) hgemm_k(
    const hf* __restrict__ A, const hf* __restrict__ B,
    void* __restrict__ Cv, const float* __restrict__ bias,
    int K, int lda, int ldb, int ldc,
    int batch2,
    long long sA1, long long sA2, long long sB1, long long sB2,
    long long sC1, long long sC2)
{
    constexpr int WARPS_N = BN / 32;
    constexpr int WARPS_M = 8 / WARPS_N;
    constexpr int MI = 128 / (WARPS_M * 16);
    constexpr int NI = 2;
    constexpr int A_LD  = 40;
    constexpr int A_ELE = 128 * A_LD;
    constexpr int B_LD  = TB ? 40 : (BN + 8);
    constexpr int B_ELE = TB ? (BN * 40) : (32 * (BN + 8));

    int z = blockIdx.z;
    int z1 = z / batch2, z2 = z - z1 * batch2;
    A += z1 * sA1 + z2 * sA2;
    B += z1 * sB1 + z2 * sB2;
    long long zC = z1 * sC1 + z2 * sC2;

    extern __shared__ char smraw[];
    hf* sA[2] = { (hf*)smraw, (hf*)smraw + A_ELE };
    hf* sB[2] = { (hf*)smraw + 2 * A_ELE, (hf*)smraw + 2 * A_ELE + B_ELE };
    float* stage = (float*)(smraw + (2 * A_ELE + 2 * B_ELE) * 2);

    const int tid  = threadIdx.x;
    const int m0   = blockIdx.y * 128, n0 = blockIdx.x * BN;
    const int warp = tid >> 5, lane = tid & 31;
    const int wm   = warp / WARPS_N, wn = warp % WARPS_N;
    const int wmB  = wm * MI * 16, wnB = wn * 32;

    wmma::fragment<wmma::accumulator, 16, 16, 16, float> acc[MI][NI];
    #pragma unroll
    for (int i = 0; i < MI; i++)
        #pragma unroll
        for (int j = 0; j < NI; j++)
            wmma::fill_fragment(acc[i][j], 0.f);

    auto loadA = [&](int buf, int k0) {
        #pragma unroll
        for (int p = 0; p < 2; p++) {
            int row = p * 64 + (tid >> 2), col = (tid & 3) * 8;
            cp16(&sA[buf][row * A_LD + col],
                 A + (long long)(m0 + row) * lda + k0 + col);
        }
    };
    auto loadB = [&](int buf, int k0) {
        if (TB) {
            #pragma unroll
            for (int p = 0; p < BN / 64; p++) {
                int row = p * 64 + (tid >> 2), col = (tid & 3) * 8;
                cp16(&sB[buf][row * B_LD + col],
                     B + (long long)(n0 + row) * ldb + k0 + col);
            }
        } else {
            constexpr int TPR = BN / 8;
            constexpr int RPP = 256 / TPR;
            #pragma unroll
            for (int p = 0; p < 32 / RPP; p++) {
                int row = p * RPP + tid / TPR;
                int col = (tid % TPR) * 8;
                cp16(&sB[buf][row * B_LD + col],
                     B + (long long)(k0 + row) * ldb + n0 + col);
            }
        }
    };
    auto compute = [&](int buf) {
        #pragma unroll
        for (int kk = 0; kk < 2; kk++) {
            wmma::fragment<wmma::matrix_a, 16, 16, 16, hf, wmma::row_major> af[MI];
            #pragma unroll
            for (int i = 0; i < MI; i++)
                wmma::load_matrix_sync(af[i],
                    &sA[buf][(wmB + i * 16) * A_LD + kk * 16], A_LD);
            #pragma unroll
            for (int j = 0; j < NI; j++) {
                if (TB) {
                    wmma::fragment<wmma::matrix_b, 16, 16, 16, hf, wmma::col_major> bfg;
                    wmma::load_matrix_sync(bfg,
                        &sB[buf][(wnB + j * 16) * B_LD + kk * 16], B_LD);
                    #pragma unroll
                    for (int i = 0; i < MI; i++)
                        wmma::mma_sync(acc[i][j], af[i], bfg, acc[i][j]);
                } else {
                    wmma::fragment<wmma::matrix_b, 16, 16, 16, hf, wmma::row_major> bfg;
                    wmma::load_matrix_sync(bfg,
                        &sB[buf][(kk * 16) * B_LD + wnB + j * 16], B_LD);
                    #pragma unroll
                    for (int i = 0; i < MI; i++)
                        wmma::mma_sync(acc[i][j], af[i], bfg, acc[i][j]);
                }
            }
        }
    };

    int buf = 0;
    loadA(0, 0); loadB(0, 0); cp_commit();
    for (int k0 = 0; k0 < K; k0 += 32) {
        asm volatile("cp.async.wait_group 0;" ::: "memory");
        __syncthreads();
        int nk = k0 + 32;
        if (nk < K) { loadA(buf ^ 1, nk); loadB(buf ^ 1, nk); }
        cp_commit();
        compute(buf);
        buf ^= 1;
    }

    if (!OUTH && EPI == 0) {
        float* Cf = (float*)Cv + zC;
        #pragma unroll
        for (int i = 0; i < MI; i++)
            #pragma unroll
            for (int j = 0; j < NI; j++) {
                int row0 = m0 + wmB + i * 16;
                int col0 = n0 + wnB + j * 16;
                wmma::store_matrix_sync(Cf + (long long)row0 * ldc + col0,
                                        acc[i][j], ldc, wmma::mem_row_major);
            }
    } else {
        float* st = stage + warp * 256;
        #pragma unroll
        for (int i = 0; i < MI; i++)
            #pragma unroll
            for (int j = 0; j < NI; j++) {
                int row0 = m0 + wmB + i * 16;
                int col0 = n0 + wnB + j * 16;
                wmma::store_matrix_sync(st, acc[i][j], 16, wmma::mem_row_major);
                __syncwarp();
                #pragma unroll
                for (int e = 0; e < 8; e++) {
                    int idx = lane * 8 + e;
                    int r = idx >> 4, c = idx & 15;
                    float v = st[idx];
                    int col = col0 + c;
                    if (EPI >= 1) v += bias[col];
                    if (EPI == 2) v = fmaxf(v, 0.f);
                    long long o = (long long)(row0 + r) * ldc + col + zC;
                    if (OUTH) ((hf*)Cv)[o] = __float2half_rn(v);
                    else      ((float*)Cv)[o] = v;
                }
                __syncwarp();
            }
    }
}

// ---------- bf16 logits GEMM with fused per-tile log-softmax partials ------
__global__ void __launch_bounds__(256) bgemm_loss_k(
    const bf* __restrict__ A, const bf* __restrict__ B,
    const int* __restrict__ target,
    float* __restrict__ pmax_out, float* __restrict__ psum_out,
    float* __restrict__ tgtlog,
    int K, int lda, int ldb)
{
    __shared__ bf sA[2][128 * 40];
    __shared__ bf sB[2][128 * 40];
    __shared__ float sPmB[128][4];
    __shared__ float sPsB[128][4];
    __shared__ float sMB[128];
    __shared__ float sStageB[8][256];

    const int tid  = threadIdx.x;
    const int m0   = blockIdx.y * 128, n0 = blockIdx.x * 128;
    const int warp = tid >> 5, lane = tid & 31;
    const int wm   = warp >> 2, wn = warp & 3;
    const int wmB  = wm * 64, wnB = wn * 32;

    wmma::fragment<wmma::accumulator, 16, 16, 16, float> acc[4][2];
    #pragma unroll
    for (int i = 0; i < 4; i++)
        #pragma unroll
        for (int j = 0; j < 2; j++)
            wmma::fill_fragment(acc[i][j], 0.f);

    auto loadAB = [&](int buf, int k0) {
        #pragma unroll
        for (int p = 0; p < 2; p++) {
            int row = p * 64 + (tid >> 2), col = (tid & 3) * 8;
            cp16(&sA[buf][row * 40 + col],
                 A + (long long)(m0 + row) * lda + k0 + col);
            cp16(&sB[buf][row * 40 + col],
                 B + (long long)(n0 + row) * ldb + k0 + col);
        }
    };
    auto compute = [&](int buf) {
        #pragma unroll
        for (int kk = 0; kk < 2; kk++) {
            wmma::fragment<wmma::matrix_a, 16, 16, 16, bf, wmma::row_major> af[4];
            #pragma unroll
            for (int i = 0; i < 4; i++)
                wmma::load_matrix_sync(af[i], &sA[buf][(wmB + i * 16) * 40 + kk * 16], 40);
            #pragma unroll
            for (int j = 0; j < 2; j++) {
                wmma::fragment<wmma::matrix_b, 16, 16, 16, bf, wmma::col_major> bfg;
                wmma::load_matrix_sync(bfg, &sB[buf][(wnB + j * 16) * 40 + kk * 16], 40);
                #pragma unroll
                for (int i = 0; i < 4; i++)
                    wmma::mma_sync(acc[i][j], af[i], bfg, acc[i][j]);
            }
        }
    };

    int buf = 0;
    loadAB(0, 0); cp_commit();
    for (int k0 = 0; k0 < K; k0 += 32) {
        asm volatile("cp.async.wait_group 0;" ::: "memory");
        __syncthreads();
        int nk = k0 + 32;
        if (nk < K) loadAB(buf ^ 1, nk);
        cp_commit();
        compute(buf);
        buf ^= 1;
    }

    float* st = sStageB[warp];
    #pragma unroll
    for (int i = 0; i < 4; i++) {
        float mx = -1e30f;
        #pragma unroll
        for (int j = 0; j < 2; j++) {
            wmma::store_matrix_sync(st, acc[i][j], 16, wmma::mem_row_major);
            __syncwarp();
            if (lane < 16) {
                #pragma unroll
                for (int c = 0; c < 16; c++) mx = fmaxf(mx, st[lane * 16 + c]);
            }
            __syncwarp();
        }
        if (lane < 16) sPmB[wmB + i * 16 + lane][wn] = mx;
    }
    __syncthreads();
    if (tid < 128)
        sMB[tid] = fmaxf(fmaxf(sPmB[tid][0], sPmB[tid][1]),
                         fmaxf(sPmB[tid][2], sPmB[tid][3]));
    __syncthreads();
    #pragma unroll
    for (int i = 0; i < 4; i++) {
        int rloc = wmB + i * 16 + (lane & 15);
        float m = sMB[rloc];
        int t = m0 + rloc;
        int tg = (lane < 16) ? target[t] : -1;
        float sme = 0.f;
        #pragma unroll
        for (int j = 0; j < 2; j++) {
            wmma::store_matrix_sync(st, acc[i][j], 16, wmma::mem_row_major);
            __syncwarp();
            if (lane < 16) {
                #pragma unroll
                for (int c = 0; c < 16; c++) {
                    float x = st[lane * 16 + c];
                    sme += expf(x - m);
                    int col = n0 + wnB + j * 16 + c;
                    if (col == tg) tgtlog[t] = x;
                }
            }
            __syncwarp();
        }
        if (lane < 16) sPsB[rloc][wn] = sme;
    }
    __syncthreads();
    if (tid < 128) {
        float s = sPsB[tid][0] + sPsB[tid][1] + sPsB[tid][2] + sPsB[tid][3];
        long long idx = (long long)(m0 + tid) * NTILE_V + blockIdx.x;
        pmax_out[idx] = sMB[tid];
        psum_out[idx] = s;
    }
}

__global__ void loss_red_k(const float* __restrict__ pmax, const float* __restrict__ psum,
                           const float* __restrict__ tgt, float* __restrict__ out)
{
    int t = blockIdx.x;
    const float* pm = pmax + (long long)t * NTILE_V;
    const float* ps = psum + (long long)t * NTILE_V;
    __shared__ float sd[128];
    int tid = threadIdx.x;
    float m = -1e30f;
    for (int j = tid; j < NTILE_V; j += 128) m = fmaxf(m, pm[j]);
    sd[tid] = m; __syncthreads();
    #pragma unroll
    for (int s = 64; s > 0; s >>= 1) {
        if (tid < s) sd[tid] = fmaxf(sd[tid], sd[tid + s]);
        __syncthreads();
    }
    m = sd[0]; __syncthreads();
    float su = 0.f;
    for (int j = tid; j < NTILE_V; j += 128) su += ps[j] * expf(pm[j] - m);
    sd[tid] = su; __syncthreads();
    #pragma unroll
    for (int s = 64; s > 0; s >>= 1) {
        if (tid < s) sd[tid] += sd[tid + s];
        __syncthreads();
    }
    if (tid == 0) out[t] = -(tgt[t] - m - logf(sd[0]));
}

// ------------------------------ small kernels ------------------------------
__global__ void conv_k(const float* __restrict__ src, bf* __restrict__ dst, int n)
{
    int i = (blockIdx.x * 256 + threadIdx.x) * 4;
    if (i < n) {
        float4 v = *(const float4*)(src + i);
        dst[i + 0] = __float2bfloat16_rn(v.x);
        dst[i + 1] = __float2bfloat16_rn(v.y);
        dst[i + 2] = __float2bfloat16_rn(v.z);
        dst[i + 3] = __float2bfloat16_rn(v.w);
    }
}

__global__ void convh_k(const float* __restrict__ src, hf* __restrict__ dst, int n)
{
    int i = (blockIdx.x * 256 + threadIdx.x) * 4;
    if (i < n) {
        float4 v = *(const float4*)(src + i);
        dst[i + 0] = __float2half_rn(v.x);
        dst[i + 1] = __float2half_rn(v.y);
        dst[i + 2] = __float2half_rn(v.z);
        dst[i + 3] = __float2half_rn(v.w);
    }
}

__global__ void embed_k(const int* __restrict__ data, const float* __restrict__ emb,
                        float* __restrict__ core, hf* __restrict__ coreH,
                        float* __restrict__ memout)
{
    int t = blockIdx.x;
    int tok = data[t];
    const float* src = emb + (long long)tok * DMODELC;
    #pragma unroll
    for (int r = 0; r < 4; r++) {
        int d = threadIdx.x + 256 * r;
        float v = src[d];
        core  [(long long)t * DMODELC + d] = v;
        coreH [(long long)t * DMODELC + d] = __float2half_rn(v);
        memout[(long long)t * DMODELC + d] = v;
    }
}

__global__ void pos_k(hf* __restrict__ posH)
{
    int k = blockIdx.x;
    float p = (float)(KLENC - 1 - k);
    #pragma unroll
    for (int r = 0; r < 4; r++) {
        int c = threadIdx.x + 256 * r;
        int j = (c < 512) ? c : (c - 512);
        float invf = 1.0f / powf(10000.0f, (2.0f * (float)j) / 1024.0f);
        float ang = p * invf;
        float v = (c < 512) ? sinf(ang) : cosf(ang);
        posH[(long long)k * DMODELC + c] = __float2half_rn(v);
    }
}

__global__ void qwqr_k(const float* __restrict__ q, const float* __restrict__ rwb,
                       const float* __restrict__ rrb,
                       hf* __restrict__ qw, hf* __restrict__ qr)
{
    long long idx = (long long)blockIdx.x * 256 + threadIdx.x;
    int c = (int)(idx & 1023);
    float v = q[idx];
    qw[idx] = __float2half_rn(v + rwb[c]);
    qr[idx] = __float2half_rn(v + rrb[c]);
}

__global__ void softmax_k(const float* __restrict__ scores, const float* __restrict__ bd,
                          hf* __restrict__ probs)
{
    int i  = blockIdx.x;
    int bn = blockIdx.y;
    int b = bn >> 4, n = bn & 15;
    const float* ac = scores + (long long)bn * (QLENC * KLENC) + (long long)i * KLENC;
    hf* pr = probs + (long long)bn * (QLENC * KLENC) + (long long)i * KLENC;
    const float* bdr = bd + (long long)n * ((long long)NT * KLENC)
                          + (long long)(i * BSZC + b) * KLENC;
    int shift = QLENC - 1 - i;
    int lim = i + 512;

    float vals[4];
    float lmax = -1e30f;
    #pragma unroll
    for (int r = 0; r < 4; r++) {
        int j = threadIdx.x + 256 * r;
        float v = -1e30f;
        if (j <= lim) v = (ac[j] + bdr[j + shift]) * 0.125f;
        vals[r] = v;
        lmax = fmaxf(lmax, v);
    }
    float rmax = block_reduce_max(lmax);
    float lsum = 0.f;
    #pragma unroll
    for (int r = 0; r < 4; r++) {
        float e = expf(vals[r] - rmax);
        vals[r] = e;
        lsum += e;
    }
    float rsum = block_reduce_sum(lsum);
    float inv = 1.0f / rsum;
    #pragma unroll
    for (int r = 0; r < 4; r++) {
        int j = threadIdx.x + 256 * r;
        pr[j] = __float2half_rn(vals[r] * inv);
    }
}

__global__ void ln_k(const float* __restrict__ x, const float* __restrict__ res,
                     const float* __restrict__ g, const float* __restrict__ bb,
                     float* __restrict__ dst, hf* __restrict__ dstH,
                     float* __restrict__ dst2)
{
    long long t = blockIdx.x;
    const float* xr = x   + t * DMODELC;
    const float* rr = res + t * DMODELC;
    float v[4];
    float s = 0.f, sq = 0.f;
    #pragma unroll
    for (int r = 0; r < 4; r++) {
        int d = threadIdx.x + 256 * r;
        float u = xr[d] + rr[d];
        v[r] = u; s += u; sq += u * u;
    }
    float sum  = block_reduce_sum(s);
    float sums = block_reduce_sum(sq);
    float mean = sum * (1.0f / 1024.0f);
    float var  = sums * (1.0f / 1024.0f) - mean * mean;
    float rstd = rsqrtf(var + 1e-5f);
    #pragma unroll
    for (int r = 0; r < 4; r++) {
        int d = threadIdx.x + 256 * r;
        float y = (v[r] - mean) * rstd * g[d] + bb[d];
        dst [t * DMODELC + d] = y;
        dstH[t * DMODELC + d] = __float2half_rn(y);
        if (dst2) dst2[t * DMODELC + d] = y;
    }
}

// ------------------------------ host dispatch ------------------------------
template<int BN, bool TB, int EPI, bool OUTH>
static inline void launch_hg(const hf* A, const hf* B, void* C,
    const float* bias, int gx, int gy, int gz,
    int K, int lda, int ldb, int ldc,
    int batch2 = 1,
    long long sA1 = 0, long long sA2 = 0,
    long long sB1 = 0, long long sB2 = 0,
    long long sC1 = 0, long long sC2 = 0)
{
    const int A_ELE = 128 * 40;
    const int B_ELE = TB ? (BN * 40) : (32 * (BN + 8));
    int smem = (2 * A_ELE + 2 * B_ELE) * 2 + 8 * 256 * 4;
    cudaFuncSetAttribute(hgemm_k<BN, TB, EPI, OUTH>,
                         cudaFuncAttributeMaxDynamicSharedMemorySize, smem);
    hgemm_k<BN, TB, EPI, OUTH><<<dim3(gx, gy, gz), 256, smem>>>(
        A, B, C, bias, K, lda, ldb, ldc, batch2, sA1, sA2, sB1, sB2, sC1, sC2);
}

extern "C" void kernel_launch(void* const* d_in, const int* in_sizes, int n_in,
                              void* d_out, int out_size)
{
    const int*   data   = (const int*)  d_in[0];
    const int*   target = (const int*)  d_in[1];
    const float* memory = (const float*)d_in[2];
    const float* emb_W  = (const float*)d_in[3];
    const float* rwb    = (const float*)d_in[4];
    const float* rrb    = (const float*)d_in[5];
    const float* Wq     = (const float*)d_in[6];
    const float* Wkv    = (const float*)d_in[7];
    const float* Wr     = (const float*)d_in[8];
    const float* Wo     = (const float*)d_in[9];
    const float* W1     = (const float*)d_in[10];
    const float* b1     = (const float*)d_in[11];
    const float* W2     = (const float*)d_in[12];
    const float* b2     = (const float*)d_in[13];
    const float* ln1g   = (const float*)d_in[14];
    const float* ln1b   = (const float*)d_in[15];
    const float* ln2g   = (const float*)d_in[16];
    const float* ln2b   = (const float*)d_in[17];
    float* out = (float*)d_out;

    float *core, *q, *scores, *bdp, *tmp, *pmax, *psum, *tgtl;
    hf *coreH, *memH, *qwH, *qrH, *kvH, *rkH, *posH, *probsH, *vecH, *h1H;
    hf *WqH, *WkvH, *WrH, *WoH, *W1H, *W2H;
    bf *embb, *coreb;
    cudaGetSymbolAddress((void**)&core,   g_core);
    cudaGetSymbolAddress((void**)&coreH,  g_coreH);
    cudaGetSymbolAddress((void**)&memH,   g_memH);
    cudaGetSymbolAddress((void**)&q,      g_q);
    cudaGetSymbolAddress((void**)&qwH,    g_qwH);
    cudaGetSymbolAddress((void**)&qrH,    g_qrH);
    cudaGetSymbolAddress((void**)&kvH,    g_kvH);
    cudaGetSymbolAddress((void**)&rkH,    g_rkH);
    cudaGetSymbolAddress((void**)&posH,   g_posH);
    cudaGetSymbolAddress((void**)&scores, g_scores);
    cudaGetSymbolAddress((void**)&bdp,    g_bd);
    cudaGetSymbolAddress((void**)&probsH, g_probsH);
    cudaGetSymbolAddress((void**)&vecH,   g_vecH);
    cudaGetSymbolAddress((void**)&tmp,    g_tmp);
    cudaGetSymbolAddress((void**)&h1H,    g_h1H);
    cudaGetSymbolAddress((void**)&pmax,   g_pmax);
    cudaGetSymbolAddress((void**)&psum,   g_psum);
    cudaGetSymbolAddress((void**)&tgtl,   g_tgt);
    cudaGetSymbolAddress((void**)&embb,   g_embb);
    cudaGetSymbolAddress((void**)&coreb,  g_coreb);
    cudaGetSymbolAddress((void**)&WqH,    g_WqH);
    cudaGetSymbolAddress((void**)&WkvH,   g_WkvH);
    cudaGetSymbolAddress((void**)&WrH,    g_WrH);
    cudaGetSymbolAddress((void**)&WoH,    g_WoH);
    cudaGetSymbolAddress((void**)&W1H,    g_W1H);
    cudaGetSymbolAddress((void**)&W2H,    g_W2H);

    const long long LSLOT = (long long)NT * DMODELC;
    float* mems_out = out + NT;

    embed_k<<<NT, 256>>>(data, emb_W, core, coreH, mems_out);
    pos_k<<<KLENC, 256>>>(posH);
    conv_k<<<(NTOKC * DMODELC) / 1024, 256>>>(emb_W, embb, NTOKC * DMODELC);
    convh_k<<<(NLAYERC * DMODELC * DMODELC) / 1024, 256>>>(Wq, WqH, NLAYERC * DMODELC * DMODELC);
    convh_k<<<(NLAYERC * DMODELC * 2 * DMODELC) / 1024, 256>>>(Wkv, WkvH, NLAYERC * DMODELC * 2 * DMODELC);
    convh_k<<<(NLAYERC * DMODELC * DMODELC) / 1024, 256>>>(Wr, WrH, NLAYERC * DMODELC * DMODELC);
    convh_k<<<(NLAYERC * DMODELC * DMODELC) / 1024, 256>>>(Wo, WoH, NLAYERC * DMODELC * DMODELC);
    convh_k<<<(NLAYERC * DMODELC * DINNERC) / 1024, 256>>>(W1, W1H, NLAYERC * DMODELC * DINNERC);
    convh_k<<<(NLAYERC * DINNERC * DMODELC) / 1024, 256>>>(W2, W2H, NLAYERC * DINNERC * DMODELC);

    for (int l = 0; l < NLAYERC; l++) {
        const hf* WqH_l  = WqH  + (long long)l * DMODELC * DMODELC;
        const hf* WkvH_l = WkvH + (long long)l * DMODELC * 2 * DMODELC;
        const hf* WrH_l  = WrH  + (long long)l * DMODELC * DMODELC;
        const hf* WoH_l  = WoH  + (long long)l * DMODELC * DMODELC;
        const hf* W1H_l  = W1H  + (long long)l * DMODELC * DINNERC;
        const hf* W2H_l  = W2H  + (long long)l * DINNERC * DMODELC;
        const float* b1_l = b1 + (long long)l * DINNERC;
        const float* b2_l = b2 + (long long)l * DMODELC;

        convh_k<<<(int)(LSLOT / 1024), 256>>>(memory + (long long)l * LSLOT,
                                              memH, (int)LSLOT);

        // kv = [memH; coreH] @ Wkv  (half out)
        launch_hg<128, false, 0, true>(memH, WkvH_l, kvH, nullptr,
            16, 32, 1, DMODELC, DMODELC, 2 * DMODELC, 2 * DMODELC);
        launch_hg<128, false, 0, true>(coreH, WkvH_l,
            kvH + (long long)NT * 2 * DMODELC, nullptr,
            16, 32, 1, DMODELC, DMODELC, 2 * DMODELC, 2 * DMODELC);

        // q = coreH @ Wq (fp32 out)
        launch_hg<128, false, 0, false>(coreH, WqH_l, q, nullptr,
            8, 32, 1, DMODELC, DMODELC, DMODELC, DMODELC);
        qwqr_k<<<(NT * DMODELC) / 256, 256>>>(q, rwb, rrb, qwH, qrH);

        // r_k = posH @ Wr (half out)
        launch_hg<128, false, 0, true>(posH, WrH_l, rkH, nullptr,
            8, 8, 1, DMODELC, DMODELC, DMODELC, DMODELC);

        // AC[b,n] = qw @ k^T  (fp32 scores)
        launch_hg<128, true, 0, false>(qwH, kvH, scores, nullptr,
            KLENC / 128, QLENC / 128, BSZC * NHEADC,
            DHEADC, BSZC * DMODELC, BSZC * 2 * DMODELC, KLENC,
            NHEADC,
            DMODELC, DHEADC,
            2 * DMODELC, DHEADC,
            (long long)NHEADC * QLENC * KLENC, (long long)QLENC * KLENC);

        // BD_raw[n] = qr @ rk^T (fp32)
        launch_hg<128, true, 0, false>(qrH, rkH, bdp, nullptr,
            KLENC / 128, NT / 128, NHEADC,
            DHEADC, DMODELC, DMODELC, KLENC,
            NHEADC,
            0, DHEADC, 0, DHEADC, 0, (long long)NT * KLENC);

        softmax_k<<<dim3(QLENC, BSZC * NHEADC), 256>>>(scores, bdp, probsH);

        // vec[b,n] = probs @ v  (BN=64, half out)
        launch_hg<64, false, 0, true>(probsH, kvH + DMODELC, vecH, nullptr,
            1, QLENC / 128, BSZC * NHEADC,
            KLENC, KLENC, BSZC * 2 * DMODELC, BSZC * DMODELC,
            NHEADC,
            (long long)NHEADC * QLENC * KLENC, (long long)QLENC * KLENC,
            2 * DMODELC, DHEADC,
            DMODELC, DHEADC);

        // attn_out = vec @ Wo (fp32)
        launch_hg<128, false, 0, false>(vecH, WoH_l, tmp, nullptr,
            8, 32, 1, DMODELC, DMODELC, DMODELC, DMODELC);

        ln_k<<<NT, 256>>>(core, tmp, ln1g + l * DMODELC, ln1b + l * DMODELC,
                          core, coreH, nullptr);

        // h1 = relu(coreH @ W1 + b1) (half out)
        launch_hg<128, false, 2, true>(coreH, W1H_l, h1H, b1_l,
            32, 32, 1, DMODELC, DMODELC, DINNERC, DINNERC);

        // ff = h1 @ W2 + b2 (fp32)
        launch_hg<128, false, 1, false>(h1H, W2H_l, tmp, b2_l,
            8, 32, 1, DINNERC, DINNERC, DMODELC, DMODELC);

        float* memout = (l < NLAYERC - 1) ? (mems_out + (long long)(l + 1) * LSLOT)
                                          : nullptr;
        ln_k<<<NT, 256>>>(core, tmp, ln2g + l * DMODELC, ln2b + l * DMODELC,
                          core, coreH, memout);
    }

    conv_k<<<(NT * DMODELC) / 1024, 256>>>(core, coreb, NT * DMODELC);
    bgemm_loss_k<<<dim3(NTILE_V, NT / 128, 1), 256>>>(
        coreb, embb, target, pmax, psum, tgtl, DMODELC, DMODELC, DMODELC);
    loss_red_k<<<NT, 128>>>(pmax, psum, tgtl, out);
}